// round 1
// baseline (speedup 1.0000x reference)
#include <cuda_runtime.h>
#include <cstddef>

#define Bb   128
#define Tt   128
#define Cc   256
#define Hh   4
#define HSz  64
#define Ll   6
#define Vv   10000
#define DFFz 1024
#define MROWS (Bb*Tt)   // 16384

// ---------------- scratch (device globals; no runtime allocation) ----------------
__device__ float g_x  [MROWS*Cc];
__device__ float g_h  [MROWS*Cc];
__device__ float g_q  [MROWS*Cc];
__device__ float g_k  [MROWS*Cc];
__device__ float g_v  [MROWS*Cc];
__device__ float g_att[MROWS*Cc];
__device__ float g_ff [MROWS*DFFz];

// ---------------- embedding: x = tok_emb[idx] + pos_emb ----------------
__global__ void embed_kernel(const int* __restrict__ idx,
                             const float* __restrict__ tok,
                             const float* __restrict__ pos,
                             float* __restrict__ x) {
    int bt = blockIdx.x;            // 0..MROWS-1
    int t  = bt % Tt;
    int tokid = idx[bt];
    int c = threadIdx.x;            // 0..255
    x[(size_t)bt*Cc + c] = tok[(size_t)tokid*Cc + c] + pos[(size_t)t*Cc + c];
}

// ---------------- layernorm: one block per row, C=256 threads ----------------
__global__ void ln_kernel(const float* __restrict__ x,
                          const float* __restrict__ gam,
                          const float* __restrict__ bet,
                          float* __restrict__ out) {
    int row = blockIdx.x;
    int tid = threadIdx.x;          // 256
    float v = x[(size_t)row*Cc + tid];
    float s = v, sq = v*v;
    #pragma unroll
    for (int o = 16; o > 0; o >>= 1) {
        s  += __shfl_xor_sync(0xFFFFFFFFu, s,  o);
        sq += __shfl_xor_sync(0xFFFFFFFFu, sq, o);
    }
    __shared__ float ws[8], wsq[8];
    if ((tid & 31) == 0) { ws[tid >> 5] = s; wsq[tid >> 5] = sq; }
    __syncthreads();
    float S = 0.f, Q = 0.f;
    #pragma unroll
    for (int i = 0; i < 8; i++) { S += ws[i]; Q += wsq[i]; }
    float mean = S * (1.0f / Cc);
    float var  = Q * (1.0f / Cc) - mean * mean;
    float inv  = rsqrtf(var + 1e-5f);
    out[(size_t)row*Cc + tid] = (v - mean) * inv * gam[tid] + bet[tid];
}

// ---------------- generic fp32 GEMM: D = [relu](A@B + bias) [+ R] ----------------
// 64x64 tile, BK=16, 256 threads, 4x4 per thread. M,K multiples of 64/16; N guarded.
__global__ void gemm_kernel(const float* __restrict__ A,
                            const float* __restrict__ Bw,
                            const float* __restrict__ bias,
                            const float* __restrict__ R,
                            float* __restrict__ D,
                            int M, int N, int K, int relu) {
    __shared__ float As[16][64];
    __shared__ float Bs[16][64];
    int tid = threadIdx.x;
    int tx  = tid & 15, ty = tid >> 4;
    int rowBase = blockIdx.y * 64;
    int colBase = blockIdx.x * 64;

    int arow = tid >> 2;            // 0..63
    int ac4  = (tid & 3) << 2;      // 0,4,8,12
    int brow = tid >> 4;            // 0..15
    int bc4  = (tid & 15) << 2;     // 0..60

    const float* Aptr = A + (size_t)(rowBase + arow) * K + ac4;
    float acc[4][4];
    #pragma unroll
    for (int i = 0; i < 4; i++)
        #pragma unroll
        for (int j = 0; j < 4; j++) acc[i][j] = 0.f;

    for (int k0 = 0; k0 < K; k0 += 16) {
        float4 av = *(const float4*)(Aptr + k0);
        As[ac4+0][arow] = av.x;
        As[ac4+1][arow] = av.y;
        As[ac4+2][arow] = av.z;
        As[ac4+3][arow] = av.w;

        int bc = colBase + bc4;
        const float* bp = Bw + (size_t)(k0 + brow) * N + bc;
        float4 bv;
        if (bc + 3 < N) {
            bv = *(const float4*)bp;
        } else {
            bv.x = (bc + 0 < N) ? bp[0] : 0.f;
            bv.y = (bc + 1 < N) ? bp[1] : 0.f;
            bv.z = (bc + 2 < N) ? bp[2] : 0.f;
            bv.w = 0.f;
        }
        *(float4*)&Bs[brow][bc4] = bv;
        __syncthreads();

        #pragma unroll
        for (int k = 0; k < 16; k++) {
            float4 a4 = *(const float4*)&As[k][ty << 2];
            float4 b4 = *(const float4*)&Bs[k][tx << 2];
            float ar[4] = {a4.x, a4.y, a4.z, a4.w};
            float br[4] = {b4.x, b4.y, b4.z, b4.w};
            #pragma unroll
            for (int i = 0; i < 4; i++)
                #pragma unroll
                for (int j = 0; j < 4; j++)
                    acc[i][j] += ar[i] * br[j];
        }
        __syncthreads();
    }

    #pragma unroll
    for (int i = 0; i < 4; i++) {
        int row = rowBase + (ty << 2) + i;
        #pragma unroll
        for (int j = 0; j < 4; j++) {
            int col = colBase + (tx << 2) + j;
            if (col < N) {
                float vv = acc[i][j];
                if (bias) vv += bias[col];
                if (relu) vv = fmaxf(vv, 0.f);
                if (R)    vv += R[(size_t)row * N + col];
                D[(size_t)row * N + col] = vv;
            }
        }
    }
}

// ---------------- fused causal attention per (b,h) block ----------------
// scores -> stable softmax -> att = P@V. 128 threads, one query row each.
#define ATTN_SMEM_FLOATS (Tt*HSz + Tt*129)
__global__ void attn_kernel(const float* __restrict__ q,
                            const float* __restrict__ k,
                            const float* __restrict__ v,
                            float* __restrict__ att) {
    extern __shared__ float smem[];
    float* kv = smem;                 // 128*64
    float* sc = smem + Tt*HSz;        // 128*129 (pad 129 -> conflict-free)
    int b = blockIdx.x >> 2;          // /H
    int h = blockIdx.x & 3;
    int tid = threadIdx.x;            // 0..127 = query row
    size_t base = (size_t)b * Tt * Cc + (size_t)h * HSz;

    // load K tile
    for (int i = tid; i < Tt*HSz; i += 128) {
        int r = i >> 6, d = i & 63;
        kv[i] = k[base + (size_t)r * Cc + d];
    }
    __syncthreads();

    // my query row into registers
    float qr[HSz];
    #pragma unroll
    for (int d = 0; d < HSz; d += 4) {
        float4 t4 = *(const float4*)&q[base + (size_t)tid * Cc + d];
        qr[d] = t4.x; qr[d+1] = t4.y; qr[d+2] = t4.z; qr[d+3] = t4.w;
    }

    const float scale = 0.0625f;      // C^-0.5 = 256^-0.5 (matches reference)
    float* myrow = sc + tid * 129;
    float mx = -1e30f;
    for (int j = 0; j <= tid; j++) {
        const float* kj = kv + j * HSz;
        float s = 0.f;
        #pragma unroll
        for (int d = 0; d < HSz; d++) s += qr[d] * kj[d];
        s *= scale;
        myrow[j] = s;
        mx = fmaxf(mx, s);
    }
    float sum = 0.f;
    for (int j = 0; j <= tid; j++) {
        float e = __expf(myrow[j] - mx);
        myrow[j] = e;
        sum += e;
    }
    float inv = 1.0f / sum;

    __syncthreads();                   // done reading K
    for (int i = tid; i < Tt*HSz; i += 128) {
        int r = i >> 6, d = i & 63;
        kv[i] = v[base + (size_t)r * Cc + d];
    }
    __syncthreads();

    float acc[HSz];
    #pragma unroll
    for (int d = 0; d < HSz; d++) acc[d] = 0.f;
    for (int j = 0; j <= tid; j++) {
        float w = myrow[j] * inv;
        const float* vj = kv + j * HSz;
        #pragma unroll
        for (int d = 0; d < HSz; d++) acc[d] += w * vj[d];
    }
    #pragma unroll
    for (int d = 0; d < HSz; d += 4) {
        float4 o; o.x = acc[d]; o.y = acc[d+1]; o.z = acc[d+2]; o.w = acc[d+3];
        *(float4*)&att[base + (size_t)tid * Cc + d] = o;
    }
}

// ---------------- host orchestration ----------------
extern "C" void kernel_launch(void* const* d_in, const int* in_sizes, int n_in,
                              void* d_out, int out_size) {
    const int*   idx    = (const int*)  d_in[0];
    const float* tok    = (const float*)d_in[1];
    const float* pos    = (const float*)d_in[2];
    const float* ln1_g  = (const float*)d_in[3];
    const float* ln1_b  = (const float*)d_in[4];
    const float* wq     = (const float*)d_in[5];
    const float* wk     = (const float*)d_in[6];
    const float* wv     = (const float*)d_in[7];
    const float* proj_w = (const float*)d_in[8];
    const float* proj_b = (const float*)d_in[9];
    const float* ln2_g  = (const float*)d_in[10];
    const float* ln2_b  = (const float*)d_in[11];
    const float* w1     = (const float*)d_in[12];
    const float* b1     = (const float*)d_in[13];
    const float* w2     = (const float*)d_in[14];
    const float* b2     = (const float*)d_in[15];
    const float* lnf_g  = (const float*)d_in[16];
    const float* lnf_b  = (const float*)d_in[17];
    const float* lm_w   = (const float*)d_in[18];
    const float* lm_b   = (const float*)d_in[19];
    float* out = (float*)d_out;

    float *x, *h, *q, *k, *v, *att, *ff;
    cudaGetSymbolAddress((void**)&x,   g_x);
    cudaGetSymbolAddress((void**)&h,   g_h);
    cudaGetSymbolAddress((void**)&q,   g_q);
    cudaGetSymbolAddress((void**)&k,   g_k);
    cudaGetSymbolAddress((void**)&v,   g_v);
    cudaGetSymbolAddress((void**)&att, g_att);
    cudaGetSymbolAddress((void**)&ff,  g_ff);

    const int attn_smem = ATTN_SMEM_FLOATS * (int)sizeof(float); // 98816 B
    cudaFuncSetAttribute(attn_kernel, cudaFuncAttributeMaxDynamicSharedMemorySize, attn_smem);

    embed_kernel<<<MROWS, Cc>>>(idx, tok, pos, x);

    dim3 gC (Cc   / 64, MROWS / 64);   // N=256
    dim3 gF (DFFz / 64, MROWS / 64);   // N=1024
    dim3 gV ((Vv + 63) / 64, MROWS / 64);

    for (int l = 0; l < Ll; l++) {
        ln_kernel<<<MROWS, Cc>>>(x, ln1_g + (size_t)l*Cc, ln1_b + (size_t)l*Cc, h);
        gemm_kernel<<<gC, 256>>>(h, wq + (size_t)l*Cc*Cc, nullptr, nullptr, q, MROWS, Cc, Cc, 0);
        gemm_kernel<<<gC, 256>>>(h, wk + (size_t)l*Cc*Cc, nullptr, nullptr, k, MROWS, Cc, Cc, 0);
        gemm_kernel<<<gC, 256>>>(h, wv + (size_t)l*Cc*Cc, nullptr, nullptr, v, MROWS, Cc, Cc, 0);
        attn_kernel<<<Bb*Hh, 128, attn_smem>>>(q, k, v, att);
        gemm_kernel<<<gC, 256>>>(att, proj_w + (size_t)l*Cc*Cc, proj_b + (size_t)l*Cc, x, x,
                                 MROWS, Cc, Cc, 0);
        ln_kernel<<<MROWS, Cc>>>(x, ln2_g + (size_t)l*Cc, ln2_b + (size_t)l*Cc, h);
        gemm_kernel<<<gF, 256>>>(h, w1 + (size_t)l*Cc*DFFz, b1 + (size_t)l*DFFz, nullptr, ff,
                                 MROWS, DFFz, Cc, 1);
        gemm_kernel<<<gC, 256>>>(ff, w2 + (size_t)l*DFFz*Cc, b2 + (size_t)l*Cc, x, x,
                                 MROWS, Cc, DFFz, 0);
    }

    ln_kernel<<<MROWS, Cc>>>(x, lnf_g, lnf_b, h);
    gemm_kernel<<<gV, 256>>>(h, lm_w, lm_b, nullptr, out, MROWS, Vv, Cc, 0);
}

// round 4
// speedup vs baseline: 1.7531x; 1.7531x over previous
#include <cuda_runtime.h>
#include <cuda_bf16.h>
#include <cstdint>
#include <cstddef>

#define Bb   128
#define Tt   128
#define Cc   256
#define Hh   4
#define HSz  64
#define Ll   6
#define Vv   10000
#define DFFz 1024
#define MROWS (Bb*Tt)   // 16384
#define VPAD 10112      // ceil(10000/128)*128

// ================= scratch (device globals) =================
__device__ __align__(256) float g_x[MROWS * Cc];
__device__ __align__(256) float g_q[MROWS * Cc];
__device__ __align__(256) float g_k[MROWS * Cc];
__device__ __align__(256) float g_v[MROWS * Cc];
__device__ __align__(256) __nv_bfloat16 g_act3 [MROWS * 3 * Cc];     // split activations [M, 768]
__device__ __align__(256) __nv_bfloat16 g_ff3  [MROWS * 3 * DFFz];   // split ff acts [M, 3072]
__device__ __align__(256) __nv_bfloat16 g_bq [Ll * Cc   * 3 * Cc];
__device__ __align__(256) __nv_bfloat16 g_bk [Ll * Cc   * 3 * Cc];
__device__ __align__(256) __nv_bfloat16 g_bv [Ll * Cc   * 3 * Cc];
__device__ __align__(256) __nv_bfloat16 g_bp [Ll * Cc   * 3 * Cc];
__device__ __align__(256) __nv_bfloat16 g_b1 [Ll * DFFz * 3 * Cc];   // [1024, 768] per layer
__device__ __align__(256) __nv_bfloat16 g_b2 [Ll * Cc   * 3 * DFFz]; // [256, 3072] per layer
__device__ __align__(256) __nv_bfloat16 g_blm[VPAD * 3 * Cc];        // [10112, 768]

// ================= small PTX helpers (all arch-agnostic, valid on sm_103) =====
__device__ __forceinline__ uint32_t smem_u32(const void* p) {
    uint32_t a;
    asm("{ .reg .u64 t; cvta.to.shared.u64 t, %1; cvt.u32.u64 %0, t; }" : "=r"(a) : "l"(p));
    return a;
}
__device__ __forceinline__ void cp_async16(uint32_t saddr, const void* gaddr) {
    asm volatile("cp.async.cg.shared.global [%0], [%1], 16;" :: "r"(saddr), "l"(gaddr));
}
__device__ __forceinline__ void cp_commit() { asm volatile("cp.async.commit_group;" ::: "memory"); }
template <int N>
__device__ __forceinline__ void cp_wait() { asm volatile("cp.async.wait_group %0;" :: "n"(N) : "memory"); }

__device__ __forceinline__ void ldm_x4(uint32_t& r0, uint32_t& r1, uint32_t& r2, uint32_t& r3,
                                       uint32_t addr) {
    asm volatile("ldmatrix.sync.aligned.m8n8.x4.shared.b16 {%0,%1,%2,%3}, [%4];"
                 : "=r"(r0), "=r"(r1), "=r"(r2), "=r"(r3) : "r"(addr));
}
__device__ __forceinline__ void mma_bf16(float* d, const uint32_t* a, const uint32_t* b) {
    asm volatile("mma.sync.aligned.m16n8k16.row.col.f32.bf16.bf16.f32 "
                 "{%0,%1,%2,%3}, {%4,%5,%6,%7}, {%8,%9}, {%0,%1,%2,%3};"
                 : "+f"(d[0]), "+f"(d[1]), "+f"(d[2]), "+f"(d[3])
                 : "r"(a[0]), "r"(a[1]), "r"(a[2]), "r"(a[3]), "r"(b[0]), "r"(b[1]));
}

// ================= embedding =================
__global__ void embed_kernel(const int* __restrict__ idx, const float* __restrict__ tok,
                             const float* __restrict__ pos, float* __restrict__ x) {
    int bt = blockIdx.x;
    int t  = bt % Tt;
    int tokid = idx[bt];
    int c = threadIdx.x;
    x[(size_t)bt * Cc + c] = tok[(size_t)tokid * Cc + c] + pos[(size_t)t * Cc + c];
}

// ================= layernorm -> split bf16 output =================
__global__ void ln_split_kernel(const float* __restrict__ x, const float* __restrict__ gam,
                                const float* __restrict__ bet, __nv_bfloat16* __restrict__ out3) {
    int row = blockIdx.x;
    int tid = threadIdx.x;
    float v = x[(size_t)row * Cc + tid];
    float s = v, sq = v * v;
    #pragma unroll
    for (int o = 16; o > 0; o >>= 1) {
        s  += __shfl_xor_sync(0xFFFFFFFFu, s,  o);
        sq += __shfl_xor_sync(0xFFFFFFFFu, sq, o);
    }
    __shared__ float ws[8], wsq[8];
    if ((tid & 31) == 0) { ws[tid >> 5] = s; wsq[tid >> 5] = sq; }
    __syncthreads();
    float S = 0.f, Q = 0.f;
    #pragma unroll
    for (int i = 0; i < 8; i++) { S += ws[i]; Q += wsq[i]; }
    float mean = S * (1.0f / Cc);
    float var  = Q * (1.0f / Cc) - mean * mean;
    float inv  = rsqrtf(var + 1e-5f);
    float y = (v - mean) * inv * gam[tid] + bet[tid];
    __nv_bfloat16 hi = __float2bfloat16(y);
    __nv_bfloat16 lo = __float2bfloat16(y - __bfloat162float(hi));
    size_t o = (size_t)row * (3 * Cc);
    out3[o + tid]          = hi;
    out3[o + Cc + tid]     = hi;
    out3[o + 2 * Cc + tid] = lo;
}

// ================= weight transpose + split: W[K,N] f32 -> out[Npad, 3K] bf16 =================
// out[n, k] = hi(W[k,n]) ; out[n, K+k] = lo(W[k,n]) ; out[n, 2K+k] = hi(W[k,n])
// pairs with activation layout [hi, hi, lo]: terms hi*hi + hi*lo + lo*hi
__global__ void wsplit_kernel(const float* __restrict__ W, __nv_bfloat16* __restrict__ out,
                              int K, int N, int Npad) {
    int l = blockIdx.z;
    W   += (size_t)l * K * N;
    out += (size_t)l * Npad * 3 * K;
    __shared__ float tile[32][33];
    int k0 = blockIdx.y * 32, n0 = blockIdx.x * 32;
    int tx = threadIdx.x, ty = threadIdx.y;   // 32 x 8
    #pragma unroll
    for (int i = 0; i < 32; i += 8) {
        int k = k0 + ty + i, n = n0 + tx;
        tile[ty + i][tx] = (n < N) ? W[(size_t)k * N + n] : 0.f;
    }
    __syncthreads();
    #pragma unroll
    for (int i = 0; i < 32; i += 8) {
        int n = n0 + ty + i, k = k0 + tx;
        float v = tile[tx][ty + i];
        __nv_bfloat16 hi = __float2bfloat16(v);
        __nv_bfloat16 lo = __float2bfloat16(v - __bfloat162float(hi));
        size_t rb = (size_t)n * 3 * K;
        out[rb + k]         = hi;
        out[rb + K + k]     = lo;
        out[rb + 2 * K + k] = hi;
    }
}

// ================= HMMA (mma.sync bf16) GEMM =================
// D[M, N] = A3[M, Kfull] @ B3[N, Kfull]^T, fp32 accum.
// CTA tile 128x128, 8 warps, warp tile 32x64. BK=64, cp.async double buffer.
#define LDA   72                       // smem row stride (elems): conflict-free ldmatrix
#define ABUF  (128 * LDA)              // 9216 elems
#define GEMM_SMEM (4 * ABUF * 2)       // 73728 bytes (As0,As1,Bs0,Bs1)

__global__ void __launch_bounds__(256)
gemm_tc(const __nv_bfloat16* __restrict__ A3, const __nv_bfloat16* __restrict__ B3,
        const float* __restrict__ bias, const float* __restrict__ Rres,
        float* __restrict__ D32, __nv_bfloat16* __restrict__ D3,
        int Kfull, int N, int relu) {
    extern __shared__ char smem_raw[];
    __nv_bfloat16* smem = (__nv_bfloat16*)smem_raw;
    uint32_t sb = smem_u32(smem);
    int tid = threadIdx.x, lane = tid & 31, wid = tid >> 5;
    int wm = wid & 3, wn = wid >> 2;      // warp grid 4(M) x 2(N)
    int bx = blockIdx.x, by = blockIdx.y;

    const __nv_bfloat16* Abase = A3 + (size_t)(by * 128) * Kfull;
    const __nv_bfloat16* Bbase = B3 + (size_t)(bx * 128) * Kfull;
    int nch = Kfull >> 6;

    float acc[2][8][4];
    #pragma unroll
    for (int mt = 0; mt < 2; mt++)
        #pragma unroll
        for (int nt = 0; nt < 8; nt++)
            #pragma unroll
            for (int i = 0; i < 4; i++) acc[mt][nt][i] = 0.f;

    // per-thread load assignment: 4 x 16B for A, 4 x 16B for B per chunk
    int lrow[4], lunit[4];
    #pragma unroll
    for (int j = 0; j < 4; j++) {
        int lin = tid + j * 256;
        lrow[j]  = lin >> 3;
        lunit[j] = (lin & 7) << 3;       // elem offset (0..56)
    }

    auto issue_load = [&](int kc, int buf) {
        const __nv_bfloat16* Ag = Abase + kc * 64;
        const __nv_bfloat16* Bg = Bbase + kc * 64;
        uint32_t sA = sb + (uint32_t)(buf * ABUF) * 2;
        uint32_t sB = sb + (uint32_t)((2 + buf) * ABUF) * 2;
        #pragma unroll
        for (int j = 0; j < 4; j++) {
            cp_async16(sA + (uint32_t)(lrow[j] * LDA + lunit[j]) * 2,
                       Ag + (size_t)lrow[j] * Kfull + lunit[j]);
            cp_async16(sB + (uint32_t)(lrow[j] * LDA + lunit[j]) * 2,
                       Bg + (size_t)lrow[j] * Kfull + lunit[j]);
        }
        cp_commit();
    };

    issue_load(0, 0);

    // precomputed fragment smem offsets
    int a_row = wm * 32 + (lane & 15);          // + mt*16
    int a_kc  = (lane >> 4) * 8;                // + ks*16
    int b_row = wn * 64 + (lane & 7) + ((lane >> 4) << 3);  // + ntp*16
    int b_kc  = (lane & 8);                     // + ks*16

    for (int kc = 0; kc < nch; kc++) {
        if (kc + 1 < nch) { issue_load(kc + 1, (kc + 1) & 1); cp_wait<1>(); }
        else             { cp_wait<0>(); }
        __syncthreads();

        uint32_t sA = sb + (uint32_t)((kc & 1) * ABUF) * 2;
        uint32_t sB = sb + (uint32_t)((2 + (kc & 1)) * ABUF) * 2;

        #pragma unroll
        for (int ks = 0; ks < 4; ks++) {
            uint32_t a[2][4], b[8][2];
            #pragma unroll
            for (int mt = 0; mt < 2; mt++) {
                uint32_t addr = sA + (uint32_t)((a_row + mt * 16) * LDA + ks * 16 + a_kc) * 2;
                ldm_x4(a[mt][0], a[mt][1], a[mt][2], a[mt][3], addr);
            }
            #pragma unroll
            for (int ntp = 0; ntp < 4; ntp++) {
                uint32_t addr = sB + (uint32_t)((b_row + ntp * 16) * LDA + ks * 16 + b_kc) * 2;
                ldm_x4(b[ntp*2][0], b[ntp*2][1], b[ntp*2+1][0], b[ntp*2+1][1], addr);
            }
            #pragma unroll
            for (int mt = 0; mt < 2; mt++)
                #pragma unroll
                for (int nt = 0; nt < 8; nt++)
                    mma_bf16(acc[mt][nt], a[mt], b[nt]);
        }
        __syncthreads();
    }

    // ---- epilogue ----
    int g = lane >> 2, tig = lane & 3;
    #pragma unroll
    for (int mt = 0; mt < 2; mt++) {
        #pragma unroll
        for (int nt = 0; nt < 8; nt++) {
            int col = bx * 128 + wn * 64 + nt * 8 + 2 * tig;
            #pragma unroll
            for (int half = 0; half < 2; half++) {       // half=0: row g, half=1: row g+8
                int row = by * 128 + wm * 32 + mt * 16 + g + half * 8;
                float v0 = acc[mt][nt][half * 2 + 0];
                float v1 = acc[mt][nt][half * 2 + 1];
                if (D32) {
                    if (col < N) {
                        float o0 = v0, o1 = v1;
                        if (bias) { o0 += bias[col]; if (col + 1 < N) o1 += bias[col + 1]; }
                        if (Rres) { o0 += Rres[(size_t)row * N + col];
                                    if (col + 1 < N) o1 += Rres[(size_t)row * N + col + 1]; }
                        D32[(size_t)row * N + col] = o0;
                        if (col + 1 < N) D32[(size_t)row * N + col + 1] = o1;
                    }
                } else {
                    size_t rb3 = (size_t)row * 3 * N;
                    #pragma unroll
                    for (int e = 0; e < 2; e++) {
                        int c = col + e;
                        float v = e ? v1 : v0;
                        if (bias) v += bias[c];
                        if (relu) v = fmaxf(v, 0.f);
                        __nv_bfloat16 hi = __float2bfloat16(v);
                        __nv_bfloat16 lo = __float2bfloat16(v - __bfloat162float(hi));
                        D3[rb3 + c]         = hi;
                        D3[rb3 + N + c]     = hi;
                        D3[rb3 + 2 * N + c] = lo;
                    }
                }
            }
        }
    }
}

// ================= fused causal attention, split bf16 output =================
#define ATTN_SMEM_FLOATS (Tt*HSz + Tt*129)
__global__ void attn_kernel(const float* __restrict__ q, const float* __restrict__ k,
                            const float* __restrict__ v, __nv_bfloat16* __restrict__ out3) {
    extern __shared__ char smem_raw[];
    float* smem = (float*)smem_raw;
    float* kv = smem;
    float* sc = smem + Tt * HSz;
    int b = blockIdx.x >> 2;
    int h = blockIdx.x & 3;
    int tid = threadIdx.x;
    size_t base = (size_t)b * Tt * Cc + (size_t)h * HSz;

    for (int i = tid; i < Tt * HSz; i += 128) {
        int r = i >> 6, d = i & 63;
        kv[i] = k[base + (size_t)r * Cc + d];
    }
    __syncthreads();

    float qr[HSz];
    #pragma unroll
    for (int d = 0; d < HSz; d += 4) {
        float4 t4 = *(const float4*)&q[base + (size_t)tid * Cc + d];
        qr[d] = t4.x; qr[d+1] = t4.y; qr[d+2] = t4.z; qr[d+3] = t4.w;
    }

    const float scale = 0.0625f;   // C^-0.5 (matches reference)
    float* myrow = sc + tid * 129;
    float mx = -1e30f;
    for (int j = 0; j <= tid; j++) {
        const float* kj = kv + j * HSz;
        float s = 0.f;
        #pragma unroll
        for (int d = 0; d < HSz; d++) s += qr[d] * kj[d];
        s *= scale;
        myrow[j] = s;
        mx = fmaxf(mx, s);
    }
    float sum = 0.f;
    for (int j = 0; j <= tid; j++) {
        float e = __expf(myrow[j] - mx);
        myrow[j] = e;
        sum += e;
    }
    float inv = 1.0f / sum;

    __syncthreads();
    for (int i = tid; i < Tt * HSz; i += 128) {
        int r = i >> 6, d = i & 63;
        kv[i] = v[base + (size_t)r * Cc + d];
    }
    __syncthreads();

    float acc[HSz];
    #pragma unroll
    for (int d = 0; d < HSz; d++) acc[d] = 0.f;
    for (int j = 0; j <= tid; j++) {
        float w = myrow[j] * inv;
        const float* vj = kv + j * HSz;
        #pragma unroll
        for (int d = 0; d < HSz; d++) acc[d] += w * vj[d];
    }
    int row = b * Tt + tid;
    size_t o = (size_t)row * (3 * Cc) + h * HSz;
    #pragma unroll
    for (int d = 0; d < HSz; d++) {
        float vv = acc[d];
        __nv_bfloat16 hi = __float2bfloat16(vv);
        __nv_bfloat16 lo = __float2bfloat16(vv - __bfloat162float(hi));
        out3[o + d]            = hi;
        out3[o + Cc + d]       = hi;
        out3[o + 2 * Cc + d]   = lo;
    }
}

// ================= host orchestration =================
extern "C" void kernel_launch(void* const* d_in, const int* in_sizes, int n_in,
                              void* d_out, int out_size) {
    const int*   idx    = (const int*)  d_in[0];
    const float* tok    = (const float*)d_in[1];
    const float* pos    = (const float*)d_in[2];
    const float* ln1_g  = (const float*)d_in[3];
    const float* ln1_b  = (const float*)d_in[4];
    const float* wq     = (const float*)d_in[5];
    const float* wk     = (const float*)d_in[6];
    const float* wv     = (const float*)d_in[7];
    const float* proj_w = (const float*)d_in[8];
    const float* proj_b = (const float*)d_in[9];
    const float* ln2_g  = (const float*)d_in[10];
    const float* ln2_b  = (const float*)d_in[11];
    const float* w1     = (const float*)d_in[12];
    const float* b1     = (const float*)d_in[13];
    const float* w2     = (const float*)d_in[14];
    const float* b2     = (const float*)d_in[15];
    const float* lnf_g  = (const float*)d_in[16];
    const float* lnf_b  = (const float*)d_in[17];
    const float* lm_w   = (const float*)d_in[18];
    const float* lm_b   = (const float*)d_in[19];
    float* out = (float*)d_out;

    float *x, *q, *k, *v;
    __nv_bfloat16 *a3, *ff3, *bq, *bk, *bv, *bp, *bw1, *bw2, *blm;
    cudaGetSymbolAddress((void**)&x,   g_x);
    cudaGetSymbolAddress((void**)&q,   g_q);
    cudaGetSymbolAddress((void**)&k,   g_k);
    cudaGetSymbolAddress((void**)&v,   g_v);
    cudaGetSymbolAddress((void**)&a3,  g_act3);
    cudaGetSymbolAddress((void**)&ff3, g_ff3);
    cudaGetSymbolAddress((void**)&bq,  g_bq);
    cudaGetSymbolAddress((void**)&bk,  g_bk);
    cudaGetSymbolAddress((void**)&bv,  g_bv);
    cudaGetSymbolAddress((void**)&bp,  g_bp);
    cudaGetSymbolAddress((void**)&bw1, g_b1);
    cudaGetSymbolAddress((void**)&bw2, g_b2);
    cudaGetSymbolAddress((void**)&blm, g_blm);

    cudaFuncSetAttribute(gemm_tc, cudaFuncAttributeMaxDynamicSharedMemorySize, GEMM_SMEM);
    const int attn_smem = ATTN_SMEM_FLOATS * (int)sizeof(float);
    cudaFuncSetAttribute(attn_kernel, cudaFuncAttributeMaxDynamicSharedMemorySize, attn_smem);

    // ---- convert + split + transpose all weights (every replay; deterministic) ----
    dim3 wbk(32, 8);
    wsplit_kernel<<<dim3(Cc/32,   Cc/32,   Ll), wbk>>>(wq,     bq,  Cc,   Cc,   Cc);
    wsplit_kernel<<<dim3(Cc/32,   Cc/32,   Ll), wbk>>>(wk,     bk,  Cc,   Cc,   Cc);
    wsplit_kernel<<<dim3(Cc/32,   Cc/32,   Ll), wbk>>>(wv,     bv,  Cc,   Cc,   Cc);
    wsplit_kernel<<<dim3(Cc/32,   Cc/32,   Ll), wbk>>>(proj_w, bp,  Cc,   Cc,   Cc);
    wsplit_kernel<<<dim3(DFFz/32, Cc/32,   Ll), wbk>>>(w1,     bw1, Cc,   DFFz, DFFz);
    wsplit_kernel<<<dim3(Cc/32,   DFFz/32, Ll), wbk>>>(w2,     bw2, DFFz, Cc,   Cc);
    wsplit_kernel<<<dim3(VPAD/32, Cc/32,   1),  wbk>>>(lm_w,   blm, Cc,   Vv,   VPAD);

    embed_kernel<<<MROWS, Cc>>>(idx, tok, pos, x);

    dim3 gC(Cc / 128,   MROWS / 128);    // (2, 128)
    dim3 gF(DFFz / 128, MROWS / 128);    // (8, 128)
    dim3 gV(VPAD / 128, MROWS / 128);    // (79, 128)
    const int K1 = 3 * Cc;      // 768
    const int K2 = 3 * DFFz;    // 3072

    for (int l = 0; l < Ll; l++) {
        ln_split_kernel<<<MROWS, Cc>>>(x, ln1_g + (size_t)l*Cc, ln1_b + (size_t)l*Cc, a3);
        gemm_tc<<<gC, 256, GEMM_SMEM>>>(a3, bq + (size_t)l*Cc*K1, nullptr, nullptr, q, nullptr, K1, Cc, 0);
        gemm_tc<<<gC, 256, GEMM_SMEM>>>(a3, bk + (size_t)l*Cc*K1, nullptr, nullptr, k, nullptr, K1, Cc, 0);
        gemm_tc<<<gC, 256, GEMM_SMEM>>>(a3, bv + (size_t)l*Cc*K1, nullptr, nullptr, v, nullptr, K1, Cc, 0);
        attn_kernel<<<Bb*Hh, 128, attn_smem>>>(q, k, v, a3);
        gemm_tc<<<gC, 256, GEMM_SMEM>>>(a3, bp + (size_t)l*Cc*K1, proj_b + (size_t)l*Cc, x, x, nullptr, K1, Cc, 0);
        ln_split_kernel<<<MROWS, Cc>>>(x, ln2_g + (size_t)l*Cc, ln2_b + (size_t)l*Cc, a3);
        gemm_tc<<<gF, 256, GEMM_SMEM>>>(a3, bw1 + (size_t)l*DFFz*K1, b1 + (size_t)l*DFFz,
                                        nullptr, nullptr, ff3, K1, DFFz, 1);
        gemm_tc<<<gC, 256, GEMM_SMEM>>>(ff3, bw2 + (size_t)l*Cc*K2, b2 + (size_t)l*Cc, x, x, nullptr, K2, Cc, 0);
    }

    ln_split_kernel<<<MROWS, Cc>>>(x, lnf_g, lnf_b, a3);
    gemm_tc<<<gV, 256, GEMM_SMEM>>>(a3, blm, lm_b, nullptr, out, nullptr, K1, Vv, 0);
}

// round 7
// speedup vs baseline: 2.7365x; 1.5610x over previous
#include <cuda_runtime.h>
#include <cuda_bf16.h>
#include <cstdint>
#include <cstddef>

#define Bb   128
#define Tt   128
#define Cc   256
#define Hh   4
#define HSz  64
#define Ll   6
#define Vv   10000
#define DFFz 1024
#define MROWS (Bb*Tt)   // 16384
#define VPAD 10112      // ceil(10000/128)*128
#define QS   (3*Cc)     // fused qkv row stride (768)
#define K1   (3*Cc)     // 768  (3-term split)
#define K2   (3*DFFz)   // 3072

// ================= scratch (device globals) =================
__device__ __align__(256) float g_x  [MROWS * Cc];
__device__ __align__(256) float g_qkv[MROWS * QS];
__device__ __align__(256) __nv_bfloat16 g_act3[MROWS * K1];           // split acts [M, 768]
__device__ __align__(256) __nv_bfloat16 g_ff3 [MROWS * K2];           // split ff acts [M, 3072]
__device__ __align__(256) __nv_bfloat16 g_bqkv[Ll * QS   * K1];       // [768, 768] per layer
__device__ __align__(256) __nv_bfloat16 g_bp  [Ll * Cc   * K1];
__device__ __align__(256) __nv_bfloat16 g_bw1 [Ll * DFFz * K1];       // [1024, 768]
__device__ __align__(256) __nv_bfloat16 g_bw2 [Ll * Cc   * K2];       // [256, 3072]
__device__ __align__(256) __nv_bfloat16 g_blm [VPAD * K1];            // [10112, 768]

// ================= PTX helpers (arch-agnostic, valid on sm_103) =====
__device__ __forceinline__ uint32_t smem_u32(const void* p) {
    uint32_t a;
    asm("{ .reg .u64 t; cvta.to.shared.u64 t, %1; cvt.u32.u64 %0, t; }" : "=r"(a) : "l"(p));
    return a;
}
__device__ __forceinline__ void cp_async16(uint32_t saddr, const void* gaddr) {
    asm volatile("cp.async.cg.shared.global [%0], [%1], 16;" :: "r"(saddr), "l"(gaddr));
}
__device__ __forceinline__ void cp_commit() { asm volatile("cp.async.commit_group;" ::: "memory"); }
template <int N>
__device__ __forceinline__ void cp_wait() { asm volatile("cp.async.wait_group %0;" :: "n"(N) : "memory"); }

__device__ __forceinline__ void ldm_x4(uint32_t& r0, uint32_t& r1, uint32_t& r2, uint32_t& r3,
                                       uint32_t addr) {
    asm volatile("ldmatrix.sync.aligned.m8n8.x4.shared.b16 {%0,%1,%2,%3}, [%4];"
                 : "=r"(r0), "=r"(r1), "=r"(r2), "=r"(r3) : "r"(addr));
}
__device__ __forceinline__ void mma_bf16(float* d, const uint32_t* a, const uint32_t* b) {
    asm volatile("mma.sync.aligned.m16n8k16.row.col.f32.bf16.bf16.f32 "
                 "{%0,%1,%2,%3}, {%4,%5,%6,%7}, {%8,%9}, {%0,%1,%2,%3};"
                 : "+f"(d[0]), "+f"(d[1]), "+f"(d[2]), "+f"(d[3])
                 : "r"(a[0]), "r"(a[1]), "r"(a[2]), "r"(a[3]), "r"(b[0]), "r"(b[1]));
}

// ================= embedding =================
__global__ void embed_kernel(const int* __restrict__ idx, const float* __restrict__ tok,
                             const float* __restrict__ pos, float* __restrict__ x) {
    int bt = blockIdx.x;
    int t  = bt % Tt;
    int tokid = idx[bt];
    int c = threadIdx.x;
    x[(size_t)bt * Cc + c] = tok[(size_t)tokid * Cc + c] + pos[(size_t)t * Cc + c];
}

// ================= layernorm -> 3-term split bf16 [M, 768] =================
// acts layout: [hi, hi, lo]  (pairs with weights [hi, lo, hi])
__global__ void ln_split_kernel(const float* __restrict__ x, const float* __restrict__ gam,
                                const float* __restrict__ bet, __nv_bfloat16* __restrict__ out3) {
    int row = blockIdx.x;
    int tid = threadIdx.x;
    float v = x[(size_t)row * Cc + tid];
    float s = v, sq = v * v;
    #pragma unroll
    for (int o = 16; o > 0; o >>= 1) {
        s  += __shfl_xor_sync(0xFFFFFFFFu, s,  o);
        sq += __shfl_xor_sync(0xFFFFFFFFu, sq, o);
    }
    __shared__ float ws[8], wsq[8];
    if ((tid & 31) == 0) { ws[tid >> 5] = s; wsq[tid >> 5] = sq; }
    __syncthreads();
    float S = 0.f, Q = 0.f;
    #pragma unroll
    for (int i = 0; i < 8; i++) { S += ws[i]; Q += wsq[i]; }
    float mean = S * (1.0f / Cc);
    float var  = Q * (1.0f / Cc) - mean * mean;
    float inv  = rsqrtf(var + 1e-5f);
    float y = (v - mean) * inv * gam[tid] + bet[tid];
    __nv_bfloat16 hi = __float2bfloat16(y);
    __nv_bfloat16 lo = __float2bfloat16(y - __bfloat162float(hi));
    size_t o = (size_t)row * K1;
    out3[o + tid]          = hi;
    out3[o + Cc + tid]     = hi;
    out3[o + 2 * Cc + tid] = lo;
}

// ================= weight transpose + split: W[K,N] f32 -> out[n, 3K] bf16 =================
// out[n, k] = hi ; out[n, K+k] = lo ; out[n, 2K+k] = hi   (weights [hi, lo, hi])
__global__ void wsplit_kernel(const float* __restrict__ W, __nv_bfloat16* __restrict__ out,
                              int K, int N, size_t lstride) {
    int l = blockIdx.z;
    W   += (size_t)l * K * N;
    out += (size_t)l * lstride;
    __shared__ float tile[32][33];
    int k0 = blockIdx.y * 32, n0 = blockIdx.x * 32;
    int tx = threadIdx.x, ty = threadIdx.y;   // 32 x 8
    #pragma unroll
    for (int i = 0; i < 32; i += 8) {
        int k = k0 + ty + i, n = n0 + tx;
        tile[ty + i][tx] = (n < N) ? W[(size_t)k * N + n] : 0.f;
    }
    __syncthreads();
    #pragma unroll
    for (int i = 0; i < 32; i += 8) {
        int n = n0 + ty + i, k = k0 + tx;
        float v = tile[tx][ty + i];
        __nv_bfloat16 hi = __float2bfloat16(v);
        __nv_bfloat16 lo = __float2bfloat16(v - __bfloat162float(hi));
        size_t rb = (size_t)n * 3 * K;
        out[rb + k]         = hi;
        out[rb + K + k]     = lo;
        out[rb + 2 * K + k] = hi;
    }
}

// ================= HMMA (mma.sync bf16) GEMM, 3-stage cp.async, 2 CTAs/SM =====
// D[M, N] = A3[M, Kfull] @ B3[N, Kfull]^T, fp32 accum.
// CTA tile 128x128, 8 warps (4Mx2N), warp tile 32x64, BK=64.
#define LDA   72
#define CHELE (128 * LDA)                  // elems per A (or B) stage buffer
#define STAGE (2 * CHELE)                  // elems per stage (A+B)
#define GEMM_SMEM (3 * STAGE * 2)          // 110592 bytes

__global__ void __launch_bounds__(256, 2)
gemm_tc(const __nv_bfloat16* __restrict__ A3, const __nv_bfloat16* __restrict__ B3,
        const float* __restrict__ bias, const float* __restrict__ Rres,
        float* __restrict__ D32, __nv_bfloat16* __restrict__ D3,
        int Kfull, int N, int relu) {
    extern __shared__ char smem_raw[];
    __nv_bfloat16* smem = (__nv_bfloat16*)smem_raw;
    uint32_t sb = smem_u32(smem);
    int tid = threadIdx.x, lane = tid & 31, wid = tid >> 5;
    int wm = wid & 3, wn = wid >> 2;
    int bx = blockIdx.x, by = blockIdx.y;

    const __nv_bfloat16* Abase = A3 + (size_t)(by * 128) * Kfull;
    const __nv_bfloat16* Bbase = B3 + (size_t)(bx * 128) * Kfull;
    int nch = Kfull >> 6;

    float acc[2][8][4];
    #pragma unroll
    for (int mt = 0; mt < 2; mt++)
        #pragma unroll
        for (int nt = 0; nt < 8; nt++)
            #pragma unroll
            for (int i = 0; i < 4; i++) acc[mt][nt][i] = 0.f;

    int lrow[4], lunit[4];
    #pragma unroll
    for (int j = 0; j < 4; j++) {
        int lin = tid + j * 256;
        lrow[j]  = lin >> 3;
        lunit[j] = (lin & 7) << 3;
    }

    auto issue_load = [&](int kc, int buf) {
        const __nv_bfloat16* Ag = Abase + kc * 64;
        const __nv_bfloat16* Bg = Bbase + kc * 64;
        uint32_t sA = sb + (uint32_t)(buf * STAGE) * 2;
        uint32_t sB = sA + (uint32_t)CHELE * 2;
        #pragma unroll
        for (int j = 0; j < 4; j++) {
            cp_async16(sA + (uint32_t)(lrow[j] * LDA + lunit[j]) * 2,
                       Ag + (size_t)lrow[j] * Kfull + lunit[j]);
            cp_async16(sB + (uint32_t)(lrow[j] * LDA + lunit[j]) * 2,
                       Bg + (size_t)lrow[j] * Kfull + lunit[j]);
        }
        cp_commit();
    };

    issue_load(0, 0);
    if (nch > 1) issue_load(1, 1);

    int a_row = wm * 32 + (lane & 15);
    int a_kc  = (lane >> 4) * 8;
    int b_row = wn * 64 + (lane & 7) + ((lane >> 4) << 3);
    int b_kc  = (lane & 8);

    for (int kc = 0; kc < nch; kc++) {
        if (kc + 1 < nch) cp_wait<1>(); else cp_wait<0>();
        __syncthreads();
        if (kc + 2 < nch) issue_load(kc + 2, (kc + 2) % 3);

        int buf = kc % 3;
        uint32_t sA = sb + (uint32_t)(buf * STAGE) * 2;
        uint32_t sB = sA + (uint32_t)CHELE * 2;

        #pragma unroll
        for (int ks = 0; ks < 4; ks++) {
            uint32_t a[2][4], b[8][2];
            #pragma unroll
            for (int mt = 0; mt < 2; mt++) {
                uint32_t addr = sA + (uint32_t)((a_row + mt * 16) * LDA + ks * 16 + a_kc) * 2;
                ldm_x4(a[mt][0], a[mt][1], a[mt][2], a[mt][3], addr);
            }
            #pragma unroll
            for (int ntp = 0; ntp < 4; ntp++) {
                uint32_t addr = sB + (uint32_t)((b_row + ntp * 16) * LDA + ks * 16 + b_kc) * 2;
                ldm_x4(b[ntp*2][0], b[ntp*2][1], b[ntp*2+1][0], b[ntp*2+1][1], addr);
            }
            #pragma unroll
            for (int mt = 0; mt < 2; mt++)
                #pragma unroll
                for (int nt = 0; nt < 8; nt++)
                    mma_bf16(acc[mt][nt], a[mt], b[nt]);
        }
        __syncthreads();
    }

    // ---- epilogue ----
    int g = lane >> 2, tig = lane & 3;
    #pragma unroll
    for (int mt = 0; mt < 2; mt++) {
        #pragma unroll
        for (int nt = 0; nt < 8; nt++) {
            int col = bx * 128 + wn * 64 + nt * 8 + 2 * tig;
            #pragma unroll
            for (int half = 0; half < 2; half++) {
                int row = by * 128 + wm * 32 + mt * 16 + g + half * 8;
                float v0 = acc[mt][nt][half * 2 + 0];
                float v1 = acc[mt][nt][half * 2 + 1];
                if (D32) {
                    if (col < N) {
                        float o0 = v0, o1 = v1;
                        if (bias) { o0 += bias[col]; if (col + 1 < N) o1 += bias[col + 1]; }
                        if (Rres) { o0 += Rres[(size_t)row * N + col];
                                    if (col + 1 < N) o1 += Rres[(size_t)row * N + col + 1]; }
                        D32[(size_t)row * N + col] = o0;
                        if (col + 1 < N) D32[(size_t)row * N + col + 1] = o1;
                    }
                } else {
                    size_t rb3 = (size_t)row * 3 * N;
                    #pragma unroll
                    for (int e = 0; e < 2; e++) {
                        int c = col + e;
                        float v = e ? v1 : v0;
                        if (bias) v += bias[c];
                        if (relu) v = fmaxf(v, 0.f);
                        __nv_bfloat16 hi = __float2bfloat16(v);
                        __nv_bfloat16 lo = __float2bfloat16(v - __bfloat162float(hi));
                        D3[rb3 + c]         = hi;
                        D3[rb3 + N + c]     = hi;
                        D3[rb3 + 2 * N + c] = lo;
                    }
                }
            }
        }
    }
}

// ================= fused causal attention (reads fused qkv), 3-term split out ======
#define ATTN_SMEM_FLOATS (Tt*HSz + Tt*129)
__global__ void attn_kernel(const float* __restrict__ qkv, __nv_bfloat16* __restrict__ out3) {
    extern __shared__ char smem_raw[];
    float* smem = (float*)smem_raw;
    float* kv = smem;
    float* sc = smem + Tt * HSz;
    int b = blockIdx.x >> 2;
    int h = blockIdx.x & 3;
    int tid = threadIdx.x;
    size_t base = (size_t)b * Tt * QS + (size_t)h * HSz;   // q cols [0,256), k +256, v +512

    for (int i = tid; i < Tt * HSz; i += 128) {
        int r = i >> 6, d = i & 63;
        kv[i] = qkv[base + Cc + (size_t)r * QS + d];       // K
    }
    __syncthreads();

    float qr[HSz];
    #pragma unroll
    for (int d = 0; d < HSz; d += 4) {
        float4 t4 = *(const float4*)&qkv[base + (size_t)tid * QS + d];
        qr[d] = t4.x; qr[d+1] = t4.y; qr[d+2] = t4.z; qr[d+3] = t4.w;
    }

    const float scale = 0.0625f;   // C^-0.5 (matches reference)
    float* myrow = sc + tid * 129;
    float mx = -1e30f;
    for (int j = 0; j <= tid; j++) {
        const float* kj = kv + j * HSz;
        float s = 0.f;
        #pragma unroll
        for (int d = 0; d < HSz; d++) s += qr[d] * kj[d];
        s *= scale;
        myrow[j] = s;
        mx = fmaxf(mx, s);
    }
    float sum = 0.f;
    for (int j = 0; j <= tid; j++) {
        float e = __expf(myrow[j] - mx);
        myrow[j] = e;
        sum += e;
    }
    float inv = 1.0f / sum;

    __syncthreads();
    for (int i = tid; i < Tt * HSz; i += 128) {
        int r = i >> 6, d = i & 63;
        kv[i] = qkv[base + 2 * Cc + (size_t)r * QS + d];   // V
    }
    __syncthreads();

    float acc[HSz];
    #pragma unroll
    for (int d = 0; d < HSz; d++) acc[d] = 0.f;
    for (int j = 0; j <= tid; j++) {
        float w = myrow[j] * inv;
        const float* vj = kv + j * HSz;
        #pragma unroll
        for (int d = 0; d < HSz; d++) acc[d] += w * vj[d];
    }
    int row = b * Tt + tid;
    size_t o = (size_t)row * K1 + h * HSz;
    #pragma unroll
    for (int d = 0; d < HSz; d++) {
        float vv = acc[d];
        __nv_bfloat16 hi = __float2bfloat16(vv);
        __nv_bfloat16 lo = __float2bfloat16(vv - __bfloat162float(hi));
        out3[o + d]          = hi;
        out3[o + Cc + d]     = hi;
        out3[o + 2 * Cc + d] = lo;
    }
}

// ================= host orchestration =================
extern "C" void kernel_launch(void* const* d_in, const int* in_sizes, int n_in,
                              void* d_out, int out_size) {
    const int*   idx    = (const int*)  d_in[0];
    const float* tok    = (const float*)d_in[1];
    const float* pos    = (const float*)d_in[2];
    const float* ln1_g  = (const float*)d_in[3];
    const float* ln1_b  = (const float*)d_in[4];
    const float* wq     = (const float*)d_in[5];
    const float* wk     = (const float*)d_in[6];
    const float* wv     = (const float*)d_in[7];
    const float* proj_w = (const float*)d_in[8];
    const float* proj_b = (const float*)d_in[9];
    const float* ln2_g  = (const float*)d_in[10];
    const float* ln2_b  = (const float*)d_in[11];
    const float* w1     = (const float*)d_in[12];
    const float* b1     = (const float*)d_in[13];
    const float* w2     = (const float*)d_in[14];
    const float* b2     = (const float*)d_in[15];
    const float* lnf_g  = (const float*)d_in[16];
    const float* lnf_b  = (const float*)d_in[17];
    const float* lm_w   = (const float*)d_in[18];
    const float* lm_b   = (const float*)d_in[19];
    float* out = (float*)d_out;

    float *x, *qkv;
    __nv_bfloat16 *a3, *ff3, *bqkv, *bp, *bw1, *bw2, *blm;
    cudaGetSymbolAddress((void**)&x,    g_x);
    cudaGetSymbolAddress((void**)&qkv,  g_qkv);
    cudaGetSymbolAddress((void**)&a3,   g_act3);
    cudaGetSymbolAddress((void**)&ff3,  g_ff3);
    cudaGetSymbolAddress((void**)&bqkv, g_bqkv);
    cudaGetSymbolAddress((void**)&bp,   g_bp);
    cudaGetSymbolAddress((void**)&bw1,  g_bw1);
    cudaGetSymbolAddress((void**)&bw2,  g_bw2);
    cudaGetSymbolAddress((void**)&blm,  g_blm);

    cudaFuncSetAttribute(gemm_tc, cudaFuncAttributeMaxDynamicSharedMemorySize, GEMM_SMEM);
    const int attn_smem = ATTN_SMEM_FLOATS * (int)sizeof(float);
    cudaFuncSetAttribute(attn_kernel, cudaFuncAttributeMaxDynamicSharedMemorySize, attn_smem);

    // ---- weight transpose + 3-term split (per replay; deterministic) ----
    dim3 wbk(32, 8);
    const size_t LQKV = (size_t)QS * K1;   // per-layer stride of fused qkv weight
    wsplit_kernel<<<dim3(Cc/32, Cc/32, Ll), wbk>>>(wq,     bqkv,                   Cc,   Cc, LQKV);
    wsplit_kernel<<<dim3(Cc/32, Cc/32, Ll), wbk>>>(wk,     bqkv + (size_t)Cc*K1,   Cc,   Cc, LQKV);
    wsplit_kernel<<<dim3(Cc/32, Cc/32, Ll), wbk>>>(wv,     bqkv + (size_t)2*Cc*K1, Cc,   Cc, LQKV);
    wsplit_kernel<<<dim3(Cc/32, Cc/32, Ll), wbk>>>(proj_w, bp,   Cc,   Cc,   (size_t)Cc*K1);
    wsplit_kernel<<<dim3(DFFz/32, Cc/32, Ll), wbk>>>(w1,   bw1,  Cc,   DFFz, (size_t)DFFz*K1);
    wsplit_kernel<<<dim3(Cc/32, DFFz/32, Ll), wbk>>>(w2,   bw2,  DFFz, Cc,   (size_t)Cc*K2);
    wsplit_kernel<<<dim3(VPAD/32, Cc/32, 1),  wbk>>>(lm_w, blm,  Cc,   Vv,   0);

    embed_kernel<<<MROWS, Cc>>>(idx, tok, pos, x);

    dim3 gQ (QS   / 128, MROWS / 128);   // (6, 128)
    dim3 gC (Cc   / 128, MROWS / 128);   // (2, 128)
    dim3 gF (DFFz / 128, MROWS / 128);   // (8, 128)
    dim3 gV (VPAD / 128, MROWS / 128);   // (79, 128)

    for (int l = 0; l < Ll; l++) {
        ln_split_kernel<<<MROWS, Cc>>>(x, ln1_g + (size_t)l*Cc, ln1_b + (size_t)l*Cc, a3);
        gemm_tc<<<gQ, 256, GEMM_SMEM>>>(a3, bqkv + (size_t)l*QS*K1, nullptr, nullptr,
                                        qkv, nullptr, K1, QS, 0);
        attn_kernel<<<Bb*Hh, 128, attn_smem>>>(qkv, a3);
        gemm_tc<<<gC, 256, GEMM_SMEM>>>(a3, bp + (size_t)l*Cc*K1, proj_b + (size_t)l*Cc,
                                        x, x, nullptr, K1, Cc, 0);
        ln_split_kernel<<<MROWS, Cc>>>(x, ln2_g + (size_t)l*Cc, ln2_b + (size_t)l*Cc, a3);
        gemm_tc<<<gF, 256, GEMM_SMEM>>>(a3, bw1 + (size_t)l*DFFz*K1, b1 + (size_t)l*DFFz,
                                        nullptr, nullptr, ff3, K1, DFFz, 1);
        gemm_tc<<<gC, 256, GEMM_SMEM>>>(ff3, bw2 + (size_t)l*Cc*K2, b2 + (size_t)l*Cc,
                                        x, x, nullptr, K2, Cc, 0);
    }

    ln_split_kernel<<<MROWS, Cc>>>(x, lnf_g, lnf_b, a3);
    gemm_tc<<<gV, 256, GEMM_SMEM>>>(a3, blm, lm_b, nullptr, out, nullptr, K1, Vv, 0);
}

// round 8
// speedup vs baseline: 2.8218x; 1.0312x over previous
#include <cuda_runtime.h>
#include <cuda_bf16.h>
#include <cuda_fp16.h>
#include <cstdint>
#include <cstddef>

#define Bb   128
#define Tt   128
#define Cc   256
#define Hh   4
#define HSz  64
#define Ll   6
#define Vv   10000
#define DFFz 1024
#define MROWS (Bb*Tt)   // 16384
#define VPAD 10112      // ceil(10000/128)*128
#define QS   (3*Cc)     // fused qkv row stride (768)
#define K1   (3*Cc)     // 768  (3-term split, layers)
#define K2   (3*DFFz)   // 3072
#define KH   (2*Cc)     // 512  (2-term fp16 split, LM head)

// ================= scratch (device globals) =================
__device__ __align__(256) float g_x  [MROWS * Cc];
__device__ __align__(256) float g_qkv[MROWS * QS];
__device__ __align__(256) __nv_bfloat16 g_act3[MROWS * K1];           // split acts [M, 768]
__device__ __align__(256) __nv_bfloat16 g_ff3 [MROWS * K2];           // split ff acts [M, 3072]
__device__ __align__(256) __nv_bfloat16 g_bqkv[Ll * QS   * K1];       // [768, 768] per layer
__device__ __align__(256) __nv_bfloat16 g_bp  [Ll * Cc   * K1];
__device__ __align__(256) __nv_bfloat16 g_bw1 [Ll * DFFz * K1];       // [1024, 768]
__device__ __align__(256) __nv_bfloat16 g_bw2 [Ll * Cc   * K2];       // [256, 3072]
__device__ __align__(256) __nv_bfloat16 g_blm [VPAD * K1];            // reused as fp16 [10112, 512]

// ================= PTX helpers (arch-agnostic, valid on sm_103) =====
__device__ __forceinline__ uint32_t smem_u32(const void* p) {
    uint32_t a;
    asm("{ .reg .u64 t; cvta.to.shared.u64 t, %1; cvt.u32.u64 %0, t; }" : "=r"(a) : "l"(p));
    return a;
}
__device__ __forceinline__ void cp_async16(uint32_t saddr, const void* gaddr) {
    asm volatile("cp.async.cg.shared.global [%0], [%1], 16;" :: "r"(saddr), "l"(gaddr));
}
__device__ __forceinline__ void cp_commit() { asm volatile("cp.async.commit_group;" ::: "memory"); }
template <int N>
__device__ __forceinline__ void cp_wait() { asm volatile("cp.async.wait_group %0;" :: "n"(N) : "memory"); }

__device__ __forceinline__ void ldm_x4(uint32_t& r0, uint32_t& r1, uint32_t& r2, uint32_t& r3,
                                       uint32_t addr) {
    asm volatile("ldmatrix.sync.aligned.m8n8.x4.shared.b16 {%0,%1,%2,%3}, [%4];"
                 : "=r"(r0), "=r"(r1), "=r"(r2), "=r"(r3) : "r"(addr));
}
__device__ __forceinline__ void mma_bf16(float* d, const uint32_t* a, const uint32_t* b) {
    asm volatile("mma.sync.aligned.m16n8k16.row.col.f32.bf16.bf16.f32 "
                 "{%0,%1,%2,%3}, {%4,%5,%6,%7}, {%8,%9}, {%0,%1,%2,%3};"
                 : "+f"(d[0]), "+f"(d[1]), "+f"(d[2]), "+f"(d[3])
                 : "r"(a[0]), "r"(a[1]), "r"(a[2]), "r"(a[3]), "r"(b[0]), "r"(b[1]));
}
__device__ __forceinline__ void mma_f16(float* d, const uint32_t* a, const uint32_t* b) {
    asm volatile("mma.sync.aligned.m16n8k16.row.col.f32.f16.f16.f32 "
                 "{%0,%1,%2,%3}, {%4,%5,%6,%7}, {%8,%9}, {%0,%1,%2,%3};"
                 : "+f"(d[0]), "+f"(d[1]), "+f"(d[2]), "+f"(d[3])
                 : "r"(a[0]), "r"(a[1]), "r"(a[2]), "r"(a[3]), "r"(b[0]), "r"(b[1]));
}

// ================= embedding =================
__global__ void embed_kernel(const int* __restrict__ idx, const float* __restrict__ tok,
                             const float* __restrict__ pos, float* __restrict__ x) {
    int bt = blockIdx.x;
    int t  = bt % Tt;
    int tokid = idx[bt];
    int c = threadIdx.x;
    x[(size_t)bt * Cc + c] = tok[(size_t)tokid * Cc + c] + pos[(size_t)t * Cc + c];
}

// ================= shared LN math =================
__device__ __forceinline__ float ln_value(const float* __restrict__ x,
                                          const float* __restrict__ gam,
                                          const float* __restrict__ bet,
                                          int row, int tid) {
    float v = x[(size_t)row * Cc + tid];
    float s = v, sq = v * v;
    #pragma unroll
    for (int o = 16; o > 0; o >>= 1) {
        s  += __shfl_xor_sync(0xFFFFFFFFu, s,  o);
        sq += __shfl_xor_sync(0xFFFFFFFFu, sq, o);
    }
    __shared__ float ws[8], wsq[8];
    if ((tid & 31) == 0) { ws[tid >> 5] = s; wsq[tid >> 5] = sq; }
    __syncthreads();
    float S = 0.f, Q = 0.f;
    #pragma unroll
    for (int i = 0; i < 8; i++) { S += ws[i]; Q += wsq[i]; }
    float mean = S * (1.0f / Cc);
    float var  = Q * (1.0f / Cc) - mean * mean;
    float inv  = rsqrtf(var + 1e-5f);
    return (v - mean) * inv * gam[tid] + bet[tid];
}

// layernorm -> 3-term split bf16 [M, 768]: acts [hi, hi, lo]
__global__ void ln_split_kernel(const float* __restrict__ x, const float* __restrict__ gam,
                                const float* __restrict__ bet, __nv_bfloat16* __restrict__ out3) {
    int row = blockIdx.x, tid = threadIdx.x;
    float y = ln_value(x, gam, bet, row, tid);
    __nv_bfloat16 hi = __float2bfloat16(y);
    __nv_bfloat16 lo = __float2bfloat16(y - __bfloat162float(hi));
    size_t o = (size_t)row * K1;
    out3[o + tid]          = hi;
    out3[o + Cc + tid]     = hi;
    out3[o + 2 * Cc + tid] = lo;
}

// final layernorm -> 2-term fp16 [M, 512]: acts [hi, lo] (exact A in fp16 pair)
__global__ void ln_split_f16_kernel(const float* __restrict__ x, const float* __restrict__ gam,
                                    const float* __restrict__ bet, __half* __restrict__ out2) {
    int row = blockIdx.x, tid = threadIdx.x;
    float y = ln_value(x, gam, bet, row, tid);
    __half hi = __float2half(y);
    __half lo = __float2half(y - __half2float(hi));
    size_t o = (size_t)row * KH;
    out2[o + tid]      = hi;
    out2[o + Cc + tid] = lo;
}

// ================= weight transpose + 3-term split (bf16): W[K,N] -> out[n, 3K] ==========
// out[n, k] = hi ; out[n, K+k] = lo ; out[n, 2K+k] = hi   (weights [hi, lo, hi])
__global__ void wsplit_kernel(const float* __restrict__ W, __nv_bfloat16* __restrict__ out,
                              int K, int N, size_t lstride) {
    int l = blockIdx.z;
    W   += (size_t)l * K * N;
    out += (size_t)l * lstride;
    __shared__ float tile[32][33];
    int k0 = blockIdx.y * 32, n0 = blockIdx.x * 32;
    int tx = threadIdx.x, ty = threadIdx.y;   // 32 x 8
    #pragma unroll
    for (int i = 0; i < 32; i += 8) {
        int k = k0 + ty + i, n = n0 + tx;
        tile[ty + i][tx] = (n < N) ? W[(size_t)k * N + n] : 0.f;
    }
    __syncthreads();
    #pragma unroll
    for (int i = 0; i < 32; i += 8) {
        int n = n0 + ty + i, k = k0 + tx;
        float v = tile[tx][ty + i];
        __nv_bfloat16 hi = __float2bfloat16(v);
        __nv_bfloat16 lo = __float2bfloat16(v - __bfloat162float(hi));
        size_t rb = (size_t)n * 3 * K;
        out[rb + k]         = hi;
        out[rb + K + k]     = lo;
        out[rb + 2 * K + k] = hi;
    }
}

// weight transpose, fp16 duplicated (LM head): W[K,N] -> out[n, 2K], both halves = fp16(W)
__global__ void wsplit_f16_kernel(const float* __restrict__ W, __half* __restrict__ out,
                                  int K, int N) {
    __shared__ float tile[32][33];
    int k0 = blockIdx.y * 32, n0 = blockIdx.x * 32;
    int tx = threadIdx.x, ty = threadIdx.y;
    #pragma unroll
    for (int i = 0; i < 32; i += 8) {
        int k = k0 + ty + i, n = n0 + tx;
        tile[ty + i][tx] = (n < N) ? W[(size_t)k * N + n] : 0.f;
    }
    __syncthreads();
    #pragma unroll
    for (int i = 0; i < 32; i += 8) {
        int n = n0 + ty + i, k = k0 + tx;
        __half h = __float2half(tile[tx][ty + i]);
        size_t rb = (size_t)n * 2 * K;
        out[rb + k]     = h;
        out[rb + K + k] = h;
    }
}

// ================= HMMA GEMM, 3-stage cp.async, 2 CTAs/SM, single sync/chunk ======
// D[M, N] = A[M, Kfull] @ B[N, Kfull]^T, fp32 accum. USE_F16 picks mma dtype.
// CTA tile 128x128, 8 warps (4Mx2N), warp tile 32x64, BK=64.
#define LDA   72
#define CHELE (128 * LDA)
#define STAGE (2 * CHELE)
#define GEMM_SMEM (3 * STAGE * 2)          // 110592 bytes

template <int USE_F16>
__global__ void __launch_bounds__(256, 2)
gemm_tc(const __nv_bfloat16* __restrict__ A3, const __nv_bfloat16* __restrict__ B3,
        const float* __restrict__ bias, const float* __restrict__ Rres,
        float* __restrict__ D32, __nv_bfloat16* __restrict__ D3,
        int Kfull, int N, int relu) {
    extern __shared__ char smem_raw[];
    uint32_t sb = smem_u32(smem_raw);
    int tid = threadIdx.x, lane = tid & 31, wid = tid >> 5;
    int wm = wid & 3, wn = wid >> 2;
    int bx = blockIdx.x, by = blockIdx.y;

    const __nv_bfloat16* Abase = A3 + (size_t)(by * 128) * Kfull;
    const __nv_bfloat16* Bbase = B3 + (size_t)(bx * 128) * Kfull;
    int nch = Kfull >> 6;

    float acc[2][8][4];
    #pragma unroll
    for (int mt = 0; mt < 2; mt++)
        #pragma unroll
        for (int nt = 0; nt < 8; nt++)
            #pragma unroll
            for (int i = 0; i < 4; i++) acc[mt][nt][i] = 0.f;

    int lrow[4], lunit[4];
    #pragma unroll
    for (int j = 0; j < 4; j++) {
        int lin = tid + j * 256;
        lrow[j]  = lin >> 3;
        lunit[j] = (lin & 7) << 3;
    }

    auto issue_load = [&](int kc, int buf) {
        const __nv_bfloat16* Ag = Abase + kc * 64;
        const __nv_bfloat16* Bg = Bbase + kc * 64;
        uint32_t sA = sb + (uint32_t)(buf * STAGE) * 2;
        uint32_t sB = sA + (uint32_t)CHELE * 2;
        #pragma unroll
        for (int j = 0; j < 4; j++) {
            cp_async16(sA + (uint32_t)(lrow[j] * LDA + lunit[j]) * 2,
                       Ag + (size_t)lrow[j] * Kfull + lunit[j]);
            cp_async16(sB + (uint32_t)(lrow[j] * LDA + lunit[j]) * 2,
                       Bg + (size_t)lrow[j] * Kfull + lunit[j]);
        }
        cp_commit();
    };

    issue_load(0, 0);
    if (nch > 1) issue_load(1, 1);

    int a_row = wm * 32 + (lane & 15);
    int a_kc  = (lane >> 4) * 8;
    int b_row = wn * 64 + (lane & 7) + ((lane >> 4) << 3);
    int b_kc  = (lane & 8);

    for (int kc = 0; kc < nch; kc++) {
        if (kc + 1 < nch) cp_wait<1>(); else cp_wait<0>();
        __syncthreads();           // single sync: orders prior reads before reissue below
        if (kc + 2 < nch) issue_load(kc + 2, (kc + 2) % 3);

        int buf = kc % 3;
        uint32_t sA = sb + (uint32_t)(buf * STAGE) * 2;
        uint32_t sB = sA + (uint32_t)CHELE * 2;

        #pragma unroll
        for (int ks = 0; ks < 4; ks++) {
            uint32_t a[2][4], b[8][2];
            #pragma unroll
            for (int mt = 0; mt < 2; mt++) {
                uint32_t addr = sA + (uint32_t)((a_row + mt * 16) * LDA + ks * 16 + a_kc) * 2;
                ldm_x4(a[mt][0], a[mt][1], a[mt][2], a[mt][3], addr);
            }
            #pragma unroll
            for (int ntp = 0; ntp < 4; ntp++) {
                uint32_t addr = sB + (uint32_t)((b_row + ntp * 16) * LDA + ks * 16 + b_kc) * 2;
                ldm_x4(b[ntp*2][0], b[ntp*2][1], b[ntp*2+1][0], b[ntp*2+1][1], addr);
            }
            #pragma unroll
            for (int mt = 0; mt < 2; mt++)
                #pragma unroll
                for (int nt = 0; nt < 8; nt++) {
                    if (USE_F16) mma_f16(acc[mt][nt], a[mt], b[nt]);
                    else         mma_bf16(acc[mt][nt], a[mt], b[nt]);
                }
        }
    }

    // ---- epilogue ----
    int g = lane >> 2, tig = lane & 3;
    #pragma unroll
    for (int mt = 0; mt < 2; mt++) {
        #pragma unroll
        for (int nt = 0; nt < 8; nt++) {
            int col = bx * 128 + wn * 64 + nt * 8 + 2 * tig;
            #pragma unroll
            for (int half = 0; half < 2; half++) {
                int row = by * 128 + wm * 32 + mt * 16 + g + half * 8;
                float v0 = acc[mt][nt][half * 2 + 0];
                float v1 = acc[mt][nt][half * 2 + 1];
                if (D32) {
                    if (col < N) {
                        float o0 = v0, o1 = v1;
                        if (bias) { o0 += bias[col]; if (col + 1 < N) o1 += bias[col + 1]; }
                        if (Rres) { o0 += Rres[(size_t)row * N + col];
                                    if (col + 1 < N) o1 += Rres[(size_t)row * N + col + 1]; }
                        D32[(size_t)row * N + col] = o0;
                        if (col + 1 < N) D32[(size_t)row * N + col + 1] = o1;
                    }
                } else {
                    size_t rb3 = (size_t)row * 3 * N;
                    #pragma unroll
                    for (int e = 0; e < 2; e++) {
                        int c = col + e;
                        float v = e ? v1 : v0;
                        if (bias) v += bias[c];
                        if (relu) v = fmaxf(v, 0.f);
                        __nv_bfloat16 hi = __float2bfloat16(v);
                        __nv_bfloat16 lo = __float2bfloat16(v - __bfloat162float(hi));
                        D3[rb3 + c]         = hi;
                        D3[rb3 + N + c]     = hi;
                        D3[rb3 + 2 * N + c] = lo;
                    }
                }
            }
        }
    }
}

// ================= fused causal attention (reads fused qkv), 3-term split out ======
#define ATTN_SMEM_FLOATS (Tt*HSz + Tt*129)
__global__ void attn_kernel(const float* __restrict__ qkv, __nv_bfloat16* __restrict__ out3) {
    extern __shared__ char smem_raw[];
    float* smem = (float*)smem_raw;
    float* kv = smem;
    float* sc = smem + Tt * HSz;
    int b = blockIdx.x >> 2;
    int h = blockIdx.x & 3;
    int tid = threadIdx.x;
    size_t base = (size_t)b * Tt * QS + (size_t)h * HSz;

    for (int i = tid; i < Tt * HSz; i += 128) {
        int r = i >> 6, d = i & 63;
        kv[i] = qkv[base + Cc + (size_t)r * QS + d];       // K
    }
    __syncthreads();

    float qr[HSz];
    #pragma unroll
    for (int d = 0; d < HSz; d += 4) {
        float4 t4 = *(const float4*)&qkv[base + (size_t)tid * QS + d];
        qr[d] = t4.x; qr[d+1] = t4.y; qr[d+2] = t4.z; qr[d+3] = t4.w;
    }

    const float scale = 0.0625f;   // C^-0.5 (matches reference)
    float* myrow = sc + tid * 129;
    float mx = -1e30f;
    for (int j = 0; j <= tid; j++) {
        const float* kj = kv + j * HSz;
        float s = 0.f;
        #pragma unroll
        for (int d = 0; d < HSz; d++) s += qr[d] * kj[d];
        s *= scale;
        myrow[j] = s;
        mx = fmaxf(mx, s);
    }
    float sum = 0.f;
    for (int j = 0; j <= tid; j++) {
        float e = __expf(myrow[j] - mx);
        myrow[j] = e;
        sum += e;
    }
    float inv = 1.0f / sum;

    __syncthreads();
    for (int i = tid; i < Tt * HSz; i += 128) {
        int r = i >> 6, d = i & 63;
        kv[i] = qkv[base + 2 * Cc + (size_t)r * QS + d];   // V
    }
    __syncthreads();

    float acc[HSz];
    #pragma unroll
    for (int d = 0; d < HSz; d++) acc[d] = 0.f;
    for (int j = 0; j <= tid; j++) {
        float w = myrow[j] * inv;
        const float* vj = kv + j * HSz;
        #pragma unroll
        for (int d = 0; d < HSz; d++) acc[d] += w * vj[d];
    }
    int row = b * Tt + tid;
    size_t o = (size_t)row * K1 + h * HSz;
    #pragma unroll
    for (int d = 0; d < HSz; d++) {
        float vv = acc[d];
        __nv_bfloat16 hi = __float2bfloat16(vv);
        __nv_bfloat16 lo = __float2bfloat16(vv - __bfloat162float(hi));
        out3[o + d]          = hi;
        out3[o + Cc + d]     = hi;
        out3[o + 2 * Cc + d] = lo;
    }
}

// ================= host orchestration =================
extern "C" void kernel_launch(void* const* d_in, const int* in_sizes, int n_in,
                              void* d_out, int out_size) {
    const int*   idx    = (const int*)  d_in[0];
    const float* tok    = (const float*)d_in[1];
    const float* pos    = (const float*)d_in[2];
    const float* ln1_g  = (const float*)d_in[3];
    const float* ln1_b  = (const float*)d_in[4];
    const float* wq     = (const float*)d_in[5];
    const float* wk     = (const float*)d_in[6];
    const float* wv     = (const float*)d_in[7];
    const float* proj_w = (const float*)d_in[8];
    const float* proj_b = (const float*)d_in[9];
    const float* ln2_g  = (const float*)d_in[10];
    const float* ln2_b  = (const float*)d_in[11];
    const float* w1     = (const float*)d_in[12];
    const float* b1     = (const float*)d_in[13];
    const float* w2     = (const float*)d_in[14];
    const float* b2     = (const float*)d_in[15];
    const float* lnf_g  = (const float*)d_in[16];
    const float* lnf_b  = (const float*)d_in[17];
    const float* lm_w   = (const float*)d_in[18];
    const float* lm_b   = (const float*)d_in[19];
    float* out = (float*)d_out;

    float *x, *qkv;
    __nv_bfloat16 *a3, *ff3, *bqkv, *bp, *bw1, *bw2, *blm;
    cudaGetSymbolAddress((void**)&x,    g_x);
    cudaGetSymbolAddress((void**)&qkv,  g_qkv);
    cudaGetSymbolAddress((void**)&a3,   g_act3);
    cudaGetSymbolAddress((void**)&ff3,  g_ff3);
    cudaGetSymbolAddress((void**)&bqkv, g_bqkv);
    cudaGetSymbolAddress((void**)&bp,   g_bp);
    cudaGetSymbolAddress((void**)&bw1,  g_bw1);
    cudaGetSymbolAddress((void**)&bw2,  g_bw2);
    cudaGetSymbolAddress((void**)&blm,  g_blm);
    __half* a2h  = (__half*)a3;    // fp16 head activations alias (fits: 768 bf16 >= 512 fp16)
    __half* blmh = (__half*)blm;   // fp16 head weights alias

    cudaFuncSetAttribute(gemm_tc<0>, cudaFuncAttributeMaxDynamicSharedMemorySize, GEMM_SMEM);
    cudaFuncSetAttribute(gemm_tc<1>, cudaFuncAttributeMaxDynamicSharedMemorySize, GEMM_SMEM);
    const int attn_smem = ATTN_SMEM_FLOATS * (int)sizeof(float);
    cudaFuncSetAttribute(attn_kernel, cudaFuncAttributeMaxDynamicSharedMemorySize, attn_smem);

    // ---- weight transpose + split (per replay; deterministic) ----
    dim3 wbk(32, 8);
    const size_t LQKV = (size_t)QS * K1;
    wsplit_kernel<<<dim3(Cc/32, Cc/32, Ll), wbk>>>(wq,     bqkv,                   Cc,   Cc, LQKV);
    wsplit_kernel<<<dim3(Cc/32, Cc/32, Ll), wbk>>>(wk,     bqkv + (size_t)Cc*K1,   Cc,   Cc, LQKV);
    wsplit_kernel<<<dim3(Cc/32, Cc/32, Ll), wbk>>>(wv,     bqkv + (size_t)2*Cc*K1, Cc,   Cc, LQKV);
    wsplit_kernel<<<dim3(Cc/32, Cc/32, Ll), wbk>>>(proj_w, bp,   Cc,   Cc,   (size_t)Cc*K1);
    wsplit_kernel<<<dim3(DFFz/32, Cc/32, Ll), wbk>>>(w1,   bw1,  Cc,   DFFz, (size_t)DFFz*K1);
    wsplit_kernel<<<dim3(Cc/32, DFFz/32, Ll), wbk>>>(w2,   bw2,  DFFz, Cc,   (size_t)Cc*K2);
    wsplit_f16_kernel<<<dim3(VPAD/32, Cc/32), wbk>>>(lm_w, blmh, Cc, Vv);

    embed_kernel<<<MROWS, Cc>>>(idx, tok, pos, x);

    dim3 gQ (QS   / 128, MROWS / 128);   // (6, 128)
    dim3 gC (Cc   / 128, MROWS / 128);   // (2, 128)
    dim3 gF (DFFz / 128, MROWS / 128);   // (8, 128)
    dim3 gV (VPAD / 128, MROWS / 128);   // (79, 128)

    for (int l = 0; l < Ll; l++) {
        ln_split_kernel<<<MROWS, Cc>>>(x, ln1_g + (size_t)l*Cc, ln1_b + (size_t)l*Cc, a3);
        gemm_tc<0><<<gQ, 256, GEMM_SMEM>>>(a3, bqkv + (size_t)l*QS*K1, nullptr, nullptr,
                                           qkv, nullptr, K1, QS, 0);
        attn_kernel<<<Bb*Hh, 128, attn_smem>>>(qkv, a3);
        gemm_tc<0><<<gC, 256, GEMM_SMEM>>>(a3, bp + (size_t)l*Cc*K1, proj_b + (size_t)l*Cc,
                                           x, x, nullptr, K1, Cc, 0);
        ln_split_kernel<<<MROWS, Cc>>>(x, ln2_g + (size_t)l*Cc, ln2_b + (size_t)l*Cc, a3);
        gemm_tc<0><<<gF, 256, GEMM_SMEM>>>(a3, bw1 + (size_t)l*DFFz*K1, b1 + (size_t)l*DFFz,
                                           nullptr, nullptr, ff3, K1, DFFz, 1);
        gemm_tc<0><<<gC, 256, GEMM_SMEM>>>(ff3, bw2 + (size_t)l*Cc*K2, b2 + (size_t)l*Cc,
                                           x, x, nullptr, K2, Cc, 0);
    }

    ln_split_f16_kernel<<<MROWS, Cc>>>(x, lnf_g, lnf_b, a2h);
    gemm_tc<1><<<gV, 256, GEMM_SMEM>>>((const __nv_bfloat16*)a2h, (const __nv_bfloat16*)blmh,
                                       lm_b, nullptr, out, nullptr, KH, Vv, 0);
}

// round 9
// speedup vs baseline: 3.7565x; 1.3312x over previous
#include <cuda_runtime.h>
#include <cuda_bf16.h>
#include <cuda_fp16.h>
#include <cstdint>
#include <cstddef>

#define Bb   128
#define Tt   128
#define Cc   256
#define Hh   4
#define HSz  64
#define Ll   6
#define Vv   10000
#define DFFz 1024
#define MROWS (Bb*Tt)   // 16384
#define VPAD 10112      // ceil(10000/128)*128
#define QS   (3*Cc)     // fused qkv row stride (768)
#define K1   (2*Cc)     // 512  (fp16 2-term split)
#define K2   (2*DFFz)   // 2048

// ================= scratch (device globals) =================
__device__ __align__(256) float g_x  [MROWS * Cc];
__device__ __align__(256) float g_qkv[MROWS * QS];
__device__ __align__(256) __half g_act2[MROWS * K1];          // split acts [M, 512]
__device__ __align__(256) __half g_ff2 [MROWS * K2];          // split ff acts [M, 2048]
__device__ __align__(256) __half g_bqkv[Ll * QS   * K1];      // [768, 512] per layer
__device__ __align__(256) __half g_bp  [Ll * Cc   * K1];
__device__ __align__(256) __half g_bw1 [Ll * DFFz * K1];      // [1024, 512]
__device__ __align__(256) __half g_bw2 [Ll * Cc   * K2];      // [256, 2048]
__device__ __align__(256) __half g_blm [VPAD * K1];           // [10112, 512]

// ================= PTX helpers (arch-agnostic, valid on sm_103) =====
__device__ __forceinline__ uint32_t smem_u32(const void* p) {
    uint32_t a;
    asm("{ .reg .u64 t; cvta.to.shared.u64 t, %1; cvt.u32.u64 %0, t; }" : "=r"(a) : "l"(p));
    return a;
}
__device__ __forceinline__ void cp_async16(uint32_t saddr, const void* gaddr) {
    asm volatile("cp.async.cg.shared.global [%0], [%1], 16;" :: "r"(saddr), "l"(gaddr));
}
__device__ __forceinline__ void cp_commit() { asm volatile("cp.async.commit_group;" ::: "memory"); }
template <int N>
__device__ __forceinline__ void cp_wait() { asm volatile("cp.async.wait_group %0;" :: "n"(N) : "memory"); }

__device__ __forceinline__ void ldm_x4(uint32_t& r0, uint32_t& r1, uint32_t& r2, uint32_t& r3,
                                       uint32_t addr) {
    asm volatile("ldmatrix.sync.aligned.m8n8.x4.shared.b16 {%0,%1,%2,%3}, [%4];"
                 : "=r"(r0), "=r"(r1), "=r"(r2), "=r"(r3) : "r"(addr));
}
__device__ __forceinline__ void mma_f16(float* d, const uint32_t* a, const uint32_t* b) {
    asm volatile("mma.sync.aligned.m16n8k16.row.col.f32.f16.f16.f32 "
                 "{%0,%1,%2,%3}, {%4,%5,%6,%7}, {%8,%9}, {%0,%1,%2,%3};"
                 : "+f"(d[0]), "+f"(d[1]), "+f"(d[2]), "+f"(d[3])
                 : "r"(a[0]), "r"(a[1]), "r"(a[2]), "r"(a[3]), "r"(b[0]), "r"(b[1]));
}

// ================= embedding =================
__global__ void embed_kernel(const int* __restrict__ idx, const float* __restrict__ tok,
                             const float* __restrict__ pos, float* __restrict__ x) {
    int bt = blockIdx.x;
    int t  = bt % Tt;
    int tokid = idx[bt];
    int c = threadIdx.x;
    x[(size_t)bt * Cc + c] = tok[(size_t)tokid * Cc + c] + pos[(size_t)t * Cc + c];
}

// ================= layernorm -> fp16 2-term split [M, 512], 2 rows/block ========
// acts [hi, lo]: exact A as fp16 pair (A = hi + lo up to 2^-23)
__global__ void ln_split_kernel(const float* __restrict__ x, const float* __restrict__ gam,
                                const float* __restrict__ bet, __half* __restrict__ out2) {
    int row = blockIdx.x * 2 + threadIdx.y;
    int tid = threadIdx.x;          // 0..255
    float v = x[(size_t)row * Cc + tid];
    float s = v, sq = v * v;
    #pragma unroll
    for (int o = 16; o > 0; o >>= 1) {
        s  += __shfl_xor_sync(0xFFFFFFFFu, s,  o);
        sq += __shfl_xor_sync(0xFFFFFFFFu, sq, o);
    }
    __shared__ float ws[2][8], wsq[2][8];
    if ((tid & 31) == 0) { ws[threadIdx.y][tid >> 5] = s; wsq[threadIdx.y][tid >> 5] = sq; }
    __syncthreads();
    float S = 0.f, Q = 0.f;
    #pragma unroll
    for (int i = 0; i < 8; i++) { S += ws[threadIdx.y][i]; Q += wsq[threadIdx.y][i]; }
    float mean = S * (1.0f / Cc);
    float var  = Q * (1.0f / Cc) - mean * mean;
    float inv  = rsqrtf(var + 1e-5f);
    float y = (v - mean) * inv * gam[tid] + bet[tid];
    __half hi = __float2half(y);
    __half lo = __float2half(y - __half2float(hi));
    size_t o = (size_t)row * K1;
    out2[o + tid]      = hi;
    out2[o + Cc + tid] = lo;
}

// ================= weight transpose, fp16 duplicated: W[K,N] -> out[n, 2K] ======
// out[n, k] = out[n, K+k] = fp16(W[k, n]); n >= N rows zero-filled
__global__ void wsplit_f16_kernel(const float* __restrict__ W, __half* __restrict__ out,
                                  int K, int N, size_t lstride) {
    int l = blockIdx.z;
    W   += (size_t)l * K * N;
    out += (size_t)l * lstride;
    __shared__ float tile[32][33];
    int k0 = blockIdx.y * 32, n0 = blockIdx.x * 32;
    int tx = threadIdx.x, ty = threadIdx.y;   // 32 x 8
    #pragma unroll
    for (int i = 0; i < 32; i += 8) {
        int k = k0 + ty + i, n = n0 + tx;
        tile[ty + i][tx] = (n < N) ? W[(size_t)k * N + n] : 0.f;
    }
    __syncthreads();
    #pragma unroll
    for (int i = 0; i < 32; i += 8) {
        int n = n0 + ty + i, k = k0 + tx;
        __half h = __float2half(tile[tx][ty + i]);
        size_t rb = (size_t)n * 2 * K;
        out[rb + k]     = h;
        out[rb + K + k] = h;
    }
}

// ================= HMMA fp16 GEMM, 3-stage cp.async, 2 CTAs/SM ==================
// D[M, N] = A2[M, Kfull] @ B2[N, Kfull]^T, fp32 accum.
// CTA tile 128x128, 8 warps (4Mx2N), warp tile 32x64, BK=64.
#define LDA   72
#define CHELE (128 * LDA)
#define STAGE (2 * CHELE)
#define GEMM_SMEM (3 * STAGE * 2)          // 110592 bytes

__global__ void __launch_bounds__(256, 2)
gemm_tc(const __half* __restrict__ A2, const __half* __restrict__ B2,
        const float* __restrict__ bias, const float* __restrict__ Rres,
        float* __restrict__ D32, __half* __restrict__ D2,
        int Kfull, int N, int relu) {
    extern __shared__ char smem_raw[];
    uint32_t sb = smem_u32(smem_raw);
    int tid = threadIdx.x, lane = tid & 31, wid = tid >> 5;
    int wm = wid & 3, wn = wid >> 2;
    int bx = blockIdx.x, by = blockIdx.y;

    const __half* Abase = A2 + (size_t)(by * 128) * Kfull;
    const __half* Bbase = B2 + (size_t)(bx * 128) * Kfull;
    int nch = Kfull >> 6;

    float acc[2][8][4];
    #pragma unroll
    for (int mt = 0; mt < 2; mt++)
        #pragma unroll
        for (int nt = 0; nt < 8; nt++)
            #pragma unroll
            for (int i = 0; i < 4; i++) acc[mt][nt][i] = 0.f;

    int lrow[4], lunit[4];
    #pragma unroll
    for (int j = 0; j < 4; j++) {
        int lin = tid + j * 256;
        lrow[j]  = lin >> 3;
        lunit[j] = (lin & 7) << 3;
    }

    auto issue_load = [&](int kc, int buf) {
        const __half* Ag = Abase + kc * 64;
        const __half* Bg = Bbase + kc * 64;
        uint32_t sA = sb + (uint32_t)(buf * STAGE) * 2;
        uint32_t sB = sA + (uint32_t)CHELE * 2;
        #pragma unroll
        for (int j = 0; j < 4; j++) {
            cp_async16(sA + (uint32_t)(lrow[j] * LDA + lunit[j]) * 2,
                       Ag + (size_t)lrow[j] * Kfull + lunit[j]);
            cp_async16(sB + (uint32_t)(lrow[j] * LDA + lunit[j]) * 2,
                       Bg + (size_t)lrow[j] * Kfull + lunit[j]);
        }
        cp_commit();
    };

    issue_load(0, 0);
    if (nch > 1) issue_load(1, 1);

    int a_row = wm * 32 + (lane & 15);
    int a_kc  = (lane >> 4) * 8;
    int b_row = wn * 64 + (lane & 7) + ((lane >> 4) << 3);
    int b_kc  = (lane & 8);

    for (int kc = 0; kc < nch; kc++) {
        if (kc + 1 < nch) cp_wait<1>(); else cp_wait<0>();
        __syncthreads();           // orders prior-buffer reads before reissue below
        if (kc + 2 < nch) issue_load(kc + 2, (kc + 2) % 3);

        int buf = kc % 3;
        uint32_t sA = sb + (uint32_t)(buf * STAGE) * 2;
        uint32_t sB = sA + (uint32_t)CHELE * 2;

        #pragma unroll
        for (int ks = 0; ks < 4; ks++) {
            uint32_t a[2][4], b[8][2];
            #pragma unroll
            for (int mt = 0; mt < 2; mt++) {
                uint32_t addr = sA + (uint32_t)((a_row + mt * 16) * LDA + ks * 16 + a_kc) * 2;
                ldm_x4(a[mt][0], a[mt][1], a[mt][2], a[mt][3], addr);
            }
            #pragma unroll
            for (int ntp = 0; ntp < 4; ntp++) {
                uint32_t addr = sB + (uint32_t)((b_row + ntp * 16) * LDA + ks * 16 + b_kc) * 2;
                ldm_x4(b[ntp*2][0], b[ntp*2][1], b[ntp*2+1][0], b[ntp*2+1][1], addr);
            }
            #pragma unroll
            for (int mt = 0; mt < 2; mt++)
                #pragma unroll
                for (int nt = 0; nt < 8; nt++)
                    mma_f16(acc[mt][nt], a[mt], b[nt]);
        }
    }

    // ---- epilogue ----
    int g = lane >> 2, tig = lane & 3;
    #pragma unroll
    for (int mt = 0; mt < 2; mt++) {
        #pragma unroll
        for (int nt = 0; nt < 8; nt++) {
            int col = bx * 128 + wn * 64 + nt * 8 + 2 * tig;
            #pragma unroll
            for (int half = 0; half < 2; half++) {
                int row = by * 128 + wm * 32 + mt * 16 + g + half * 8;
                float v0 = acc[mt][nt][half * 2 + 0];
                float v1 = acc[mt][nt][half * 2 + 1];
                if (D32) {
                    if (col < N) {
                        float o0 = v0, o1 = v1;
                        if (bias) { o0 += bias[col]; if (col + 1 < N) o1 += bias[col + 1]; }
                        if (Rres) { o0 += Rres[(size_t)row * N + col];
                                    if (col + 1 < N) o1 += Rres[(size_t)row * N + col + 1]; }
                        D32[(size_t)row * N + col] = o0;
                        if (col + 1 < N) D32[(size_t)row * N + col + 1] = o1;
                    }
                } else {
                    size_t rb2 = (size_t)row * 2 * N;
                    #pragma unroll
                    for (int e = 0; e < 2; e++) {
                        int c = col + e;
                        float v = e ? v1 : v0;
                        if (bias) v += bias[c];
                        if (relu) v = fmaxf(v, 0.f);
                        __half hi = __float2half(v);
                        __half lo = __float2half(v - __half2float(hi));
                        D2[rb2 + c]     = hi;
                        D2[rb2 + N + c] = lo;
                    }
                }
            }
        }
    }
}

// ================= fused causal attention (reads fused qkv), fp16 2-term out ======
#define ATTN_SMEM_FLOATS (Tt*HSz + Tt*129)
__global__ void attn_kernel(const float* __restrict__ qkv, __half* __restrict__ out2) {
    extern __shared__ char smem_raw[];
    float* smem = (float*)smem_raw;
    float* kv = smem;
    float* sc = smem + Tt * HSz;
    int b = blockIdx.x >> 2;
    int h = blockIdx.x & 3;
    int tid = threadIdx.x;
    size_t base = (size_t)b * Tt * QS + (size_t)h * HSz;

    for (int i = tid; i < Tt * HSz; i += 128) {
        int r = i >> 6, d = i & 63;
        kv[i] = qkv[base + Cc + (size_t)r * QS + d];       // K
    }
    __syncthreads();

    float qr[HSz];
    #pragma unroll
    for (int d = 0; d < HSz; d += 4) {
        float4 t4 = *(const float4*)&qkv[base + (size_t)tid * QS + d];
        qr[d] = t4.x; qr[d+1] = t4.y; qr[d+2] = t4.z; qr[d+3] = t4.w;
    }

    const float scale = 0.0625f;   // C^-0.5 (matches reference)
    float* myrow = sc + tid * 129;
    float mx = -1e30f;
    for (int j = 0; j <= tid; j++) {
        const float* kj = kv + j * HSz;
        float s = 0.f;
        #pragma unroll
        for (int d = 0; d < HSz; d++) s += qr[d] * kj[d];
        s *= scale;
        myrow[j] = s;
        mx = fmaxf(mx, s);
    }
    float sum = 0.f;
    for (int j = 0; j <= tid; j++) {
        float e = __expf(myrow[j] - mx);
        myrow[j] = e;
        sum += e;
    }
    float inv = 1.0f / sum;

    __syncthreads();
    for (int i = tid; i < Tt * HSz; i += 128) {
        int r = i >> 6, d = i & 63;
        kv[i] = qkv[base + 2 * Cc + (size_t)r * QS + d];   // V
    }
    __syncthreads();

    float acc[HSz];
    #pragma unroll
    for (int d = 0; d < HSz; d++) acc[d] = 0.f;
    for (int j = 0; j <= tid; j++) {
        float w = myrow[j] * inv;
        const float* vj = kv + j * HSz;
        #pragma unroll
        for (int d = 0; d < HSz; d++) acc[d] += w * vj[d];
    }
    int row = b * Tt + tid;
    size_t o = (size_t)row * K1 + h * HSz;
    #pragma unroll
    for (int d = 0; d < HSz; d++) {
        float vv = acc[d];
        __half hi = __float2half(vv);
        __half lo = __float2half(vv - __half2float(hi));
        out2[o + d]      = hi;
        out2[o + Cc + d] = lo;
    }
}

// ================= host orchestration =================
extern "C" void kernel_launch(void* const* d_in, const int* in_sizes, int n_in,
                              void* d_out, int out_size) {
    const int*   idx    = (const int*)  d_in[0];
    const float* tok    = (const float*)d_in[1];
    const float* pos    = (const float*)d_in[2];
    const float* ln1_g  = (const float*)d_in[3];
    const float* ln1_b  = (const float*)d_in[4];
    const float* wq     = (const float*)d_in[5];
    const float* wk     = (const float*)d_in[6];
    const float* wv     = (const float*)d_in[7];
    const float* proj_w = (const float*)d_in[8];
    const float* proj_b = (const float*)d_in[9];
    const float* ln2_g  = (const float*)d_in[10];
    const float* ln2_b  = (const float*)d_in[11];
    const float* w1     = (const float*)d_in[12];
    const float* b1     = (const float*)d_in[13];
    const float* w2     = (const float*)d_in[14];
    const float* b2     = (const float*)d_in[15];
    const float* lnf_g  = (const float*)d_in[16];
    const float* lnf_b  = (const float*)d_in[17];
    const float* lm_w   = (const float*)d_in[18];
    const float* lm_b   = (const float*)d_in[19];
    float* out = (float*)d_out;

    float *x, *qkv;
    __half *a2, *ff2, *bqkv, *bp, *bw1, *bw2, *blm;
    cudaGetSymbolAddress((void**)&x,    g_x);
    cudaGetSymbolAddress((void**)&qkv,  g_qkv);
    cudaGetSymbolAddress((void**)&a2,   g_act2);
    cudaGetSymbolAddress((void**)&ff2,  g_ff2);
    cudaGetSymbolAddress((void**)&bqkv, g_bqkv);
    cudaGetSymbolAddress((void**)&bp,   g_bp);
    cudaGetSymbolAddress((void**)&bw1,  g_bw1);
    cudaGetSymbolAddress((void**)&bw2,  g_bw2);
    cudaGetSymbolAddress((void**)&blm,  g_blm);

    cudaFuncSetAttribute(gemm_tc, cudaFuncAttributeMaxDynamicSharedMemorySize, GEMM_SMEM);
    const int attn_smem = ATTN_SMEM_FLOATS * (int)sizeof(float);
    cudaFuncSetAttribute(attn_kernel, cudaFuncAttributeMaxDynamicSharedMemorySize, attn_smem);

    // ---- weight transpose to fp16 duplicated [n, 2K] (per replay; deterministic) ----
    dim3 wbk(32, 8);
    const size_t LQKV = (size_t)QS * K1;
    wsplit_f16_kernel<<<dim3(Cc/32, Cc/32, Ll), wbk>>>(wq,     bqkv,                   Cc,   Cc, LQKV);
    wsplit_f16_kernel<<<dim3(Cc/32, Cc/32, Ll), wbk>>>(wk,     bqkv + (size_t)Cc*K1,   Cc,   Cc, LQKV);
    wsplit_f16_kernel<<<dim3(Cc/32, Cc/32, Ll), wbk>>>(wv,     bqkv + (size_t)2*Cc*K1, Cc,   Cc, LQKV);
    wsplit_f16_kernel<<<dim3(Cc/32, Cc/32, Ll), wbk>>>(proj_w, bp,   Cc,   Cc, (size_t)Cc*K1);
    wsplit_f16_kernel<<<dim3(DFFz/32, Cc/32, Ll), wbk>>>(w1,   bw1,  Cc,   DFFz, (size_t)DFFz*K1);
    wsplit_f16_kernel<<<dim3(Cc/32, DFFz/32, Ll), wbk>>>(w2,   bw2,  DFFz, Cc, (size_t)Cc*K2);
    wsplit_f16_kernel<<<dim3(VPAD/32, Cc/32, 1),  wbk>>>(lm_w, blm,  Cc,   Vv, 0);

    embed_kernel<<<MROWS, Cc>>>(idx, tok, pos, x);

    dim3 lnb(256, 2);
    dim3 gQ (QS   / 128, MROWS / 128);   // (6, 128)
    dim3 gC (Cc   / 128, MROWS / 128);   // (2, 128)
    dim3 gF (DFFz / 128, MROWS / 128);   // (8, 128)
    dim3 gV (VPAD / 128, MROWS / 128);   // (79, 128)

    for (int l = 0; l < Ll; l++) {
        ln_split_kernel<<<MROWS/2, lnb>>>(x, ln1_g + (size_t)l*Cc, ln1_b + (size_t)l*Cc, a2);
        gemm_tc<<<gQ, 256, GEMM_SMEM>>>(a2, bqkv + (size_t)l*LQKV, nullptr, nullptr,
                                        qkv, nullptr, K1, QS, 0);
        attn_kernel<<<Bb*Hh, 128, attn_smem>>>(qkv, a2);
        gemm_tc<<<gC, 256, GEMM_SMEM>>>(a2, bp + (size_t)l*Cc*K1, proj_b + (size_t)l*Cc,
                                        x, x, nullptr, K1, Cc, 0);
        ln_split_kernel<<<MROWS/2, lnb>>>(x, ln2_g + (size_t)l*Cc, ln2_b + (size_t)l*Cc, a2);
        gemm_tc<<<gF, 256, GEMM_SMEM>>>(a2, bw1 + (size_t)l*DFFz*K1, b1 + (size_t)l*DFFz,
                                        nullptr, nullptr, ff2, K1, DFFz, 1);
        gemm_tc<<<gC, 256, GEMM_SMEM>>>(ff2, bw2 + (size_t)l*Cc*K2, b2 + (size_t)l*Cc,
                                        x, x, nullptr, K2, Cc, 0);
    }

    ln_split_kernel<<<MROWS/2, lnb>>>(x, lnf_g, lnf_b, a2);
    gemm_tc<<<gV, 256, GEMM_SMEM>>>(a2, blm, lm_b, nullptr, out, nullptr, K1, Vv, 0);
}